// round 6
// baseline (speedup 1.0000x reference)
#include <cuda_runtime.h>
#include <cuda_bf16.h>
#include <stdint.h>

#define N_NODES 50000
#define N_EDGES 800000
#define ND 128
#define ED 64
#define HID 320

typedef uint32_t u32;

// ---------------- device globals (allocation-guard safe) -------------------
__device__ float g_P[(size_t)N_NODES * 512];     // node projections [N,512] fp32
__device__ __nv_bfloat16 g_WnH[512 * 128];       // node weights hi  [j][k]
__device__ __nv_bfloat16 g_WnL[512 * 128];       // node weights lo
__device__ __nv_bfloat16 g_WeH[256 * 64];        // edge weights hi  [j][k]
__device__ __nv_bfloat16 g_WeL[256 * 64];        // edge weights lo

// ---------------- helpers ----------------------------------------------------
__device__ __forceinline__ u32 smem_u32(const void* p) {
    u32 a;
    asm("{ .reg .u64 t; cvta.to.shared.u64 t, %1; cvt.u32.u64 %0, t; }" : "=r"(a) : "l"(p));
    return a;
}
__device__ __forceinline__ void ldsm4(u32 addr, u32& r0, u32& r1, u32& r2, u32& r3) {
    asm volatile("ldmatrix.sync.aligned.m8n8.x4.shared.b16 {%0,%1,%2,%3}, [%4];"
                 : "=r"(r0), "=r"(r1), "=r"(r2), "=r"(r3) : "r"(addr));
}
__device__ __forceinline__ void mma16816(float* d, u32 a0, u32 a1, u32 a2, u32 a3,
                                         u32 b0, u32 b1) {
    asm volatile(
        "mma.sync.aligned.m16n8k16.row.col.f32.bf16.bf16.f32 "
        "{%0,%1,%2,%3}, {%4,%5,%6,%7}, {%8,%9}, {%0,%1,%2,%3};"
        : "+f"(d[0]), "+f"(d[1]), "+f"(d[2]), "+f"(d[3])
        : "r"(a0), "r"(a1), "r"(a2), "r"(a3), "r"(b0), "r"(b1));
}
__device__ __forceinline__ void red4(float* p, float a, float b, float c, float d) {
    asm volatile("red.global.add.v4.f32 [%0], {%1,%2,%3,%4};"
                 :: "l"(p), "f"(a), "f"(b), "f"(c), "f"(d) : "memory");
}
__device__ __forceinline__ void split_bf16(float v, __nv_bfloat16& h, __nv_bfloat16& l) {
    h = __float2bfloat16_rn(v);
    l = __float2bfloat16_rn(v - __bfloat162float(h));
}
__device__ __forceinline__ float softplus_f(float x) {
    return fmaxf(x, 0.f) + __logf(1.f + __expf(-fabsf(x)));
}
__device__ __forceinline__ float sigmoid_f(float x) {
    return __fdividef(1.f, 1.f + __expf(-x));
}

// ---------------------------------------------------------------------------
// pack: bf16 hi/lo weights with column permutation
// ---------------------------------------------------------------------------
__global__ void pack_weights_kernel(const float* __restrict__ Wv,
                                    const float* __restrict__ Wm) {
    int i = blockIdx.x * blockDim.x + threadIdx.x;
    if (i < 512 * 128) {
        int j = i >> 7, k = i & 127;
        float v;
        if (j < 128)      v = Wv[j * HID + k];
        else if (j < 256) v = Wv[(j - 128) * HID + 128 + k];
        else if (j < 384) v = Wm[(j - 256) * HID + k];
        else              v = Wm[(j - 384) * HID + 128 + k];
        __nv_bfloat16 h, l; split_bf16(v, h, l);
        g_WnH[i] = h; g_WnL[i] = l;
    }
    if (i < 256 * 64) {
        int j = i >> 6, k = i & 63;
        float v = (j < 128) ? Wv[j * HID + 256 + k] : Wm[(j - 128) * HID + 256 + k];
        __nv_bfloat16 h, l; split_bf16(v, h, l);
        g_WeH[i] = h; g_WeL[i] = l;
    }
}

__global__ void zero_out_kernel(float4* __restrict__ out, int n4) {
    int i = blockIdx.x * blockDim.x + threadIdx.x;
    if (i < n4) out[i] = make_float4(0.f, 0.f, 0.f, 0.f);
}

// ---------------------------------------------------------------------------
// Node GEMM (HMMA bf16x3, 2 CTAs/SM): tile 64 nodes x 128 j, grid (148, 4).
// 512 thr = 16 warps; warp = 16n x 32j (egrp = wid>>2, jgrp = wid&3).
// ---------------------------------------------------------------------------
#define NSTR 136                     // padded bf16 row stride
#define N_BH 0
#define N_BL 34816
#define N_AH 69632
#define N_AL 87040
#define NODE_SMEM 104448

__global__ __launch_bounds__(512, 2) void node_gemm_kernel(const float* __restrict__ X) {
    extern __shared__ char smem[];
    u32 sb = smem_u32(smem);
    int tid = threadIdx.x, wid = tid >> 5, lane = tid & 31;
    int n0 = blockIdx.y * 128;

    // fill B (Wn quarter [128 j][128 k]) hi/lo, padded rows
    {
        int j = tid >> 2, k0 = (tid & 3) * 32;
        #pragma unroll
        for (int c = 0; c < 32; c += 2) {
            __nv_bfloat162 h2, l2;
            h2.x = g_WnH[(n0 + j) * 128 + k0 + c];
            h2.y = g_WnH[(n0 + j) * 128 + k0 + c + 1];
            l2.x = g_WnL[(n0 + j) * 128 + k0 + c];
            l2.y = g_WnL[(n0 + j) * 128 + k0 + c + 1];
            *(__nv_bfloat162*)(smem + N_BH + (j * NSTR + k0 + c) * 2) = h2;
            *(__nv_bfloat162*)(smem + N_BL + (j * NSTR + k0 + c) * 2) = l2;
        }
    }

    int egrp = wid >> 2, jgrp = wid & 3;
    u32 aH = sb + N_AH + ((egrp * 16 + (lane & 15)) * NSTR + (lane >> 4) * 8) * 2;
    u32 aL = sb + N_AL + ((egrp * 16 + (lane & 15)) * NSTR + (lane >> 4) * 8) * 2;
    // ldsm4 B: lane groups -> (ntpair-sub, k-half): j = jgrp*32 + ((lane>>4)&1)*8 + (lane&7)
    u32 bBH = sb + N_BH + ((jgrp * 32 + ((lane >> 4) & 1) * 8 + (lane & 7)) * NSTR
                           + ((lane >> 3) & 1) * 8) * 2;
    u32 bBL = bBH + (N_BL - N_BH);

    const int ntiles = (N_NODES + 63) / 64;   // 782
    for (int t = blockIdx.x; t < ntiles; t += gridDim.x) {
        int m0 = t * 64;
        // fill A (X tile [64][128]) hi/lo
        {
            int row = tid >> 3, k0 = (tid & 7) * 16;
            int gm = m0 + row;
            #pragma unroll
            for (int c = 0; c < 16; c += 2) {
                float2 xv = make_float2(0.f, 0.f);
                if (gm < N_NODES) xv = *(const float2*)&X[(size_t)gm * ND + k0 + c];
                __nv_bfloat16 h0, l0, h1, l1;
                split_bf16(xv.x, h0, l0); split_bf16(xv.y, h1, l1);
                *(__nv_bfloat162*)(smem + N_AH + (row * NSTR + k0 + c) * 2) = __nv_bfloat162(h0, h1);
                *(__nv_bfloat162*)(smem + N_AL + (row * NSTR + k0 + c) * 2) = __nv_bfloat162(l0, l1);
            }
        }
        __syncthreads();

        float acc[4][4];
        #pragma unroll
        for (int i = 0; i < 4; i++)
            #pragma unroll
            for (int j = 0; j < 4; j++) acc[i][j] = 0.f;

        #pragma unroll
        for (int kk = 0; kk < 8; kk++) {
            u32 ah0, ah1, ah2, ah3, al0, al1, al2, al3;
            ldsm4(aH + kk * 32, ah0, ah1, ah2, ah3);
            ldsm4(aL + kk * 32, al0, al1, al2, al3);
            #pragma unroll
            for (int np = 0; np < 2; np++) {
                u32 bh0, bh1, bh2, bh3, bl0, bl1, bl2, bl3;
                ldsm4(bBH + np * (16 * NSTR * 2) + kk * 32, bh0, bh1, bh2, bh3);
                ldsm4(bBL + np * (16 * NSTR * 2) + kk * 32, bl0, bl1, bl2, bl3);
                mma16816(acc[np * 2 + 0], ah0, ah1, ah2, ah3, bh0, bh1);
                mma16816(acc[np * 2 + 0], al0, al1, al2, al3, bh0, bh1);
                mma16816(acc[np * 2 + 0], ah0, ah1, ah2, ah3, bl0, bl1);
                mma16816(acc[np * 2 + 1], ah0, ah1, ah2, ah3, bh2, bh3);
                mma16816(acc[np * 2 + 1], al0, al1, al2, al3, bh2, bh3);
                mma16816(acc[np * 2 + 1], ah0, ah1, ah2, ah3, bl2, bl3);
            }
        }

        // store D directly to g_P
        int nodeLo = m0 + egrp * 16 + (lane >> 2);
        int jbase = n0 + jgrp * 32 + (lane & 3) * 2;
        #pragma unroll
        for (int nt = 0; nt < 4; nt++) {
            if (nodeLo < N_NODES)
                *(float2*)&g_P[(size_t)nodeLo * 512 + jbase + nt * 8] =
                    make_float2(acc[nt][0], acc[nt][1]);
            if (nodeLo + 8 < N_NODES)
                *(float2*)&g_P[(size_t)(nodeLo + 8) * 512 + jbase + nt * 8] =
                    make_float2(acc[nt][2], acc[nt][3]);
        }
        __syncthreads();
    }
}

// ---------------------------------------------------------------------------
// Edge kernel (persistent, HMMA bf16x3, 2 CTAs/SM):
//   tile = 32 edges; D[32,256] = ef @ We^T (hi/lo x3) staged to smem;
//   epilogue warp-per-edge: coalesced P gathers, activations, red.v4 scatter.
// 512 thr = 16 warps; warp = 16e x 32j (egrp = wid>>3, jgrp = wid&7).
// B in xor-swizzled 128B rows (no padding); A padded stride 72.
// ---------------------------------------------------------------------------
#define ESTR 72
#define E_BH 0                       // 256*128 = 32768
#define E_BL 32768
#define E_AH 65536                   // 32*72*2 = 4608
#define E_AL 70144
#define E_STG 74752                  // 32 * 260 * 4 = 33280
#define E_IDX 108032                 // 64 ints
#define EDGE_SMEM 108288

__global__ __launch_bounds__(512, 2) void edge_kernel(
    const float* __restrict__ ef, const int* __restrict__ ei,
    const float* __restrict__ b_val, const float* __restrict__ b_mul,
    float* __restrict__ out)
{
    extern __shared__ char smem[];
    u32 sb = smem_u32(smem);
    int tid = threadIdx.x, wid = tid >> 5, lane = tid & 31;
    float* stgf = (float*)(smem + E_STG);
    int* s_sh = (int*)(smem + E_IDX);
    int* r_sh = s_sh + 32;

    // fill B (We [256 j][64 k]) hi/lo once, xor-swizzled 128B rows
    {
        int j = tid >> 1, k0 = (tid & 1) * 32;
        int xj = (j & 7) << 4;
        #pragma unroll
        for (int c = 0; c < 32; c += 2) {
            int kb = (k0 + c) * 2;
            u32 off = (u32)(j * 128) + (u32)(kb ^ xj);
            __nv_bfloat162 h2, l2;
            h2.x = g_WeH[j * 64 + k0 + c]; h2.y = g_WeH[j * 64 + k0 + c + 1];
            l2.x = g_WeL[j * 64 + k0 + c]; l2.y = g_WeL[j * 64 + k0 + c + 1];
            *(__nv_bfloat162*)(smem + E_BH + off) = h2;
            *(__nv_bfloat162*)(smem + E_BL + off) = l2;
        }
    }

    const float4 bv4 = *(const float4*)&b_val[4 * lane];
    const float4 bm4 = *(const float4*)&b_mul[4 * lane];

    int egrp = wid >> 3, jgrp = wid & 7;
    u32 aH = sb + E_AH + ((egrp * 16 + (lane & 15)) * ESTR + (lane >> 4) * 8) * 2;
    u32 aL = sb + E_AL + ((egrp * 16 + (lane & 15)) * ESTR + (lane >> 4) * 8) * 2;
    // ldsm4 B lane mapping: j = jgrp*32 + ((lane>>4)&1)*8 + (lane&7), khalf = (lane>>3)&1
    int jrow = jgrp * 32 + ((lane >> 4) & 1) * 8 + (lane & 7);
    u32 bRowH = sb + E_BH + (u32)(jrow * 128);
    int xorj = (jrow & 7) << 4;
    int kl16 = ((lane >> 3) & 1) * 16;

    const int ntiles = N_EDGES / 32;   // 25000
    for (int tile = blockIdx.x; tile < ntiles; tile += gridDim.x) {
        int e0 = tile * 32;
        if (tid < 32)       s_sh[tid] = ei[e0 + tid];
        else if (tid < 64)  r_sh[tid - 32] = ei[N_EDGES + e0 + tid - 32];

        // fill A (ef tile [32][64]) hi/lo
        {
            int e = tid >> 4, k0 = (tid & 15) * 4;
            const float2* src = (const float2*)&ef[(size_t)(e0 + e) * ED + k0];
            #pragma unroll
            for (int c = 0; c < 4; c += 2) {
                float2 xv = src[c >> 1];
                __nv_bfloat16 h0, l0, h1, l1;
                split_bf16(xv.x, h0, l0); split_bf16(xv.y, h1, l1);
                *(__nv_bfloat162*)(smem + E_AH + (e * ESTR + k0 + c) * 2) = __nv_bfloat162(h0, h1);
                *(__nv_bfloat162*)(smem + E_AL + (e * ESTR + k0 + c) * 2) = __nv_bfloat162(l0, l1);
            }
        }
        __syncthreads();

        float acc[4][4];
        #pragma unroll
        for (int i = 0; i < 4; i++)
            #pragma unroll
            for (int j = 0; j < 4; j++) acc[i][j] = 0.f;

        #pragma unroll
        for (int kk = 0; kk < 4; kk++) {
            u32 ah0, ah1, ah2, ah3, al0, al1, al2, al3;
            ldsm4(aH + kk * 32, ah0, ah1, ah2, ah3);
            ldsm4(aL + kk * 32, al0, al1, al2, al3);
            u32 kx = (u32)((kk * 32 + kl16) ^ xorj);
            #pragma unroll
            for (int np = 0; np < 2; np++) {
                u32 bh0, bh1, bh2, bh3, bl0, bl1, bl2, bl3;
                ldsm4(bRowH + np * 2048 + kx, bh0, bh1, bh2, bh3);
                ldsm4(bRowH + 32768 + np * 2048 + kx, bl0, bl1, bl2, bl3);
                mma16816(acc[np * 2 + 0], ah0, ah1, ah2, ah3, bh0, bh1);
                mma16816(acc[np * 2 + 0], al0, al1, al2, al3, bh0, bh1);
                mma16816(acc[np * 2 + 0], ah0, ah1, ah2, ah3, bl0, bl1);
                mma16816(acc[np * 2 + 1], ah0, ah1, ah2, ah3, bh2, bh3);
                mma16816(acc[np * 2 + 1], al0, al1, al2, al3, bh2, bh3);
                mma16816(acc[np * 2 + 1], ah0, ah1, ah2, ah3, bl2, bl3);
            }
        }

        // stage D -> smem (row stride 260 floats)
        {
            int eLo = egrp * 16 + (lane >> 2);
            int jb = jgrp * 32 + (lane & 3) * 2;
            #pragma unroll
            for (int nt = 0; nt < 4; nt++) {
                *(float2*)&stgf[eLo * 260 + jb + nt * 8] = make_float2(acc[nt][0], acc[nt][1]);
                *(float2*)&stgf[(eLo + 8) * 260 + jb + nt * 8] = make_float2(acc[nt][2], acc[nt][3]);
            }
        }
        __syncthreads();

        // epilogue: warp-per-edge (2 iterations x 16 warps = 32 edges)
        #pragma unroll 1
        for (int it = 0; it < 2; it++) {
            int e = it * 16 + wid;
            float4 dv = *(const float4*)&stgf[e * 260 + 4 * lane];
            float4 dm = *(const float4*)&stgf[e * 260 + 128 + 4 * lane];
            int s = s_sh[e];
            int r = r_sh[e];
            const float4 psv = *(const float4*)&g_P[(size_t)s * 512 + 4 * lane];
            const float4 prv = *(const float4*)&g_P[(size_t)r * 512 + 128 + 4 * lane];
            const float4 psm = *(const float4*)&g_P[(size_t)s * 512 + 256 + 4 * lane];
            const float4 prm = *(const float4*)&g_P[(size_t)r * 512 + 384 + 4 * lane];

            float v0 = dv.x + psv.x + prv.x + bv4.x;
            float v1 = dv.y + psv.y + prv.y + bv4.y;
            float v2 = dv.z + psv.z + prv.z + bv4.z;
            float v3 = dv.w + psv.w + prv.w + bv4.w;
            float m0 = dm.x + psm.x + prm.x + bm4.x;
            float m1 = dm.y + psm.y + prm.y + bm4.y;
            float m2 = dm.z + psm.z + prm.z + bm4.z;
            float m3 = dm.w + psm.w + prm.w + bm4.w;

            float g0 = softplus_f(v0) * sigmoid_f(m0);
            float g1 = softplus_f(v1) * sigmoid_f(m1);
            float g2 = softplus_f(v2) * sigmoid_f(m2);
            float g3 = softplus_f(v3) * sigmoid_f(m3);

            red4(out + (size_t)r * ND + 4 * lane, g0, g1, g2, g3);
        }
        __syncthreads();
    }
}

// ---------------------------------------------------------------------------
extern "C" void kernel_launch(void* const* d_in, const int* in_sizes, int n_in,
                              void* d_out, int out_size) {
    const float* x  = (const float*)d_in[0];
    const int*   ei = (const int*)  d_in[1];
    const float* ef = (const float*)d_in[2];
    const float* Wv = (const float*)d_in[3];
    const float* bv = (const float*)d_in[4];
    const float* Wm = (const float*)d_in[5];
    const float* bm = (const float*)d_in[6];
    float* out = (float*)d_out;

    cudaFuncSetAttribute(node_gemm_kernel,
                         cudaFuncAttributeMaxDynamicSharedMemorySize, NODE_SMEM);
    cudaFuncSetAttribute(edge_kernel,
                         cudaFuncAttributeMaxDynamicSharedMemorySize, EDGE_SMEM);

    pack_weights_kernel<<<256, 256>>>(Wv, Wm);

    int n4 = N_NODES * ND / 4;
    zero_out_kernel<<<(n4 + 255) / 256, 256>>>((float4*)out, n4);

    node_gemm_kernel<<<dim3(148, 4), 512, NODE_SMEM>>>(x);

    edge_kernel<<<296, 512, EDGE_SMEM>>>(ef, ei, bv, bm, out);
}

// round 7
// speedup vs baseline: 1.1840x; 1.1840x over previous
#include <cuda_runtime.h>
#include <cuda_bf16.h>
#include <stdint.h>

#define N_NODES 50000
#define N_EDGES 800000
#define ND 128
#define ED 64
#define HID 320

typedef uint32_t u32;

// ---------------- device globals (allocation-guard safe) -------------------
__device__ float g_P[(size_t)N_NODES * 512];     // node projections [N,512] fp32
__device__ __nv_bfloat16 g_WnH[512 * 128];       // node weights hi  [j][k]
__device__ __nv_bfloat16 g_WnL[512 * 128];       // node weights lo
__device__ __nv_bfloat16 g_WeH[256 * 64];        // edge weights hi  [j][k]
__device__ __nv_bfloat16 g_WeL[256 * 64];        // edge weights lo

// ---------------- helpers ----------------------------------------------------
__device__ __forceinline__ u32 smem_u32(const void* p) {
    u32 a;
    asm("{ .reg .u64 t; cvta.to.shared.u64 t, %1; cvt.u32.u64 %0, t; }" : "=r"(a) : "l"(p));
    return a;
}
__device__ __forceinline__ void ldsm4(u32 addr, u32& r0, u32& r1, u32& r2, u32& r3) {
    asm volatile("ldmatrix.sync.aligned.m8n8.x4.shared.b16 {%0,%1,%2,%3}, [%4];"
                 : "=r"(r0), "=r"(r1), "=r"(r2), "=r"(r3) : "r"(addr));
}
__device__ __forceinline__ void ldsm2(u32 addr, u32& r0, u32& r1) {
    asm volatile("ldmatrix.sync.aligned.m8n8.x2.shared.b16 {%0,%1}, [%2];"
                 : "=r"(r0), "=r"(r1) : "r"(addr));
}
__device__ __forceinline__ void mma16816(float* d, u32 a0, u32 a1, u32 a2, u32 a3,
                                         u32 b0, u32 b1) {
    asm volatile(
        "mma.sync.aligned.m16n8k16.row.col.f32.bf16.bf16.f32 "
        "{%0,%1,%2,%3}, {%4,%5,%6,%7}, {%8,%9}, {%0,%1,%2,%3};"
        : "+f"(d[0]), "+f"(d[1]), "+f"(d[2]), "+f"(d[3])
        : "r"(a0), "r"(a1), "r"(a2), "r"(a3), "r"(b0), "r"(b1));
}
__device__ __forceinline__ void red4(float* p, float a, float b, float c, float d) {
    asm volatile("red.global.add.v4.f32 [%0], {%1,%2,%3,%4};"
                 :: "l"(p), "f"(a), "f"(b), "f"(c), "f"(d) : "memory");
}
__device__ __forceinline__ void split_bf16(float v, __nv_bfloat16& h, __nv_bfloat16& l) {
    h = __float2bfloat16_rn(v);
    l = __float2bfloat16_rn(v - __bfloat162float(h));
}
__device__ __forceinline__ float softplus_f(float x) {
    return fmaxf(x, 0.f) + __logf(1.f + __expf(-fabsf(x)));
}
__device__ __forceinline__ float sigmoid_f(float x) {
    return __fdividef(1.f, 1.f + __expf(-x));
}

// ---------------------------------------------------------------------------
// pack: bf16 hi/lo weights with column permutation
// ---------------------------------------------------------------------------
__global__ void pack_weights_kernel(const float* __restrict__ Wv,
                                    const float* __restrict__ Wm) {
    int i = blockIdx.x * blockDim.x + threadIdx.x;
    if (i < 512 * 128) {
        int j = i >> 7, k = i & 127;
        float v;
        if (j < 128)      v = Wv[j * HID + k];
        else if (j < 256) v = Wv[(j - 128) * HID + 128 + k];
        else if (j < 384) v = Wm[(j - 256) * HID + k];
        else              v = Wm[(j - 384) * HID + 128 + k];
        __nv_bfloat16 h, l; split_bf16(v, h, l);
        g_WnH[i] = h; g_WnL[i] = l;
    }
    if (i < 256 * 64) {
        int j = i >> 6, k = i & 63;
        float v = (j < 128) ? Wv[j * HID + 256 + k] : Wm[(j - 128) * HID + 256 + k];
        __nv_bfloat16 h, l; split_bf16(v, h, l);
        g_WeH[i] = h; g_WeL[i] = l;
    }
}

__global__ void zero_out_kernel(float4* __restrict__ out, int n4) {
    int i = blockIdx.x * blockDim.x + threadIdx.x;
    if (i < n4) out[i] = make_float4(0.f, 0.f, 0.f, 0.f);
}

// ---------------------------------------------------------------------------
// Node GEMM (HMMA bf16x3) — R4 configuration (known good):
// tile 128 nodes x 256 j, 512 thr = 16 warps, warp = 16n x 128j.
// ---------------------------------------------------------------------------
#define NSTR 136
#define N_BH 0
#define N_BL 69632
#define N_AH 139264
#define N_AL 174080
#define NODE_SMEM 208896

__global__ __launch_bounds__(512, 1) void node_gemm_kernel(const float* __restrict__ X) {
    extern __shared__ char smem[];
    u32 sb = smem_u32(smem);
    int tid = threadIdx.x, wid = tid >> 5, lane = tid & 31;
    int n0 = blockIdx.y * 256;

    {
        int j = tid >> 1, k0 = (tid & 1) * 64;
        #pragma unroll
        for (int c = 0; c < 64; c += 2) {
            __nv_bfloat162 h2, l2;
            h2.x = g_WnH[(n0 + j) * 128 + k0 + c];
            h2.y = g_WnH[(n0 + j) * 128 + k0 + c + 1];
            l2.x = g_WnL[(n0 + j) * 128 + k0 + c];
            l2.y = g_WnL[(n0 + j) * 128 + k0 + c + 1];
            *(__nv_bfloat162*)(smem + N_BH + (j * NSTR + k0 + c) * 2) = h2;
            *(__nv_bfloat162*)(smem + N_BL + (j * NSTR + k0 + c) * 2) = l2;
        }
    }

    int egrp = wid >> 1, jgrp = wid & 1;
    u32 aH = sb + N_AH + ((egrp * 16 + (lane & 15)) * NSTR + (lane >> 4) * 8) * 2;
    u32 aL = sb + N_AL + ((egrp * 16 + (lane & 15)) * NSTR + (lane >> 4) * 8) * 2;
    u32 bH = sb + N_BH + ((jgrp * 128 + (lane & 7)) * NSTR + (lane & 8)) * 2;
    u32 bL = sb + N_BL + ((jgrp * 128 + (lane & 7)) * NSTR + (lane & 8)) * 2;

    const int ntiles = (N_NODES + 127) / 128;   // 391
    for (int t = blockIdx.x; t < ntiles; t += gridDim.x) {
        int m0 = t * 128;
        {
            int row = tid >> 2, k0 = (tid & 3) * 32;
            int gm = m0 + row;
            #pragma unroll
            for (int c = 0; c < 32; c += 2) {
                float2 xv = make_float2(0.f, 0.f);
                if (gm < N_NODES) xv = *(const float2*)&X[(size_t)gm * ND + k0 + c];
                __nv_bfloat16 h0, l0, h1, l1;
                split_bf16(xv.x, h0, l0); split_bf16(xv.y, h1, l1);
                *(__nv_bfloat162*)(smem + N_AH + (row * NSTR + k0 + c) * 2) = __nv_bfloat162(h0, h1);
                *(__nv_bfloat162*)(smem + N_AL + (row * NSTR + k0 + c) * 2) = __nv_bfloat162(l0, l1);
            }
        }
        __syncthreads();

        float acc[16][4];
        #pragma unroll
        for (int i = 0; i < 16; i++)
            #pragma unroll
            for (int j = 0; j < 4; j++) acc[i][j] = 0.f;

        #pragma unroll
        for (int kk = 0; kk < 8; kk++) {
            u32 ah0, ah1, ah2, ah3, al0, al1, al2, al3;
            ldsm4(aH + kk * 32, ah0, ah1, ah2, ah3);
            ldsm4(aL + kk * 32, al0, al1, al2, al3);
            #pragma unroll
            for (int nt = 0; nt < 16; nt++) {
                u32 bh0, bh1, bl0, bl1;
                ldsm2(bH + nt * (8 * NSTR * 2) + kk * 32, bh0, bh1);
                ldsm2(bL + nt * (8 * NSTR * 2) + kk * 32, bl0, bl1);
                mma16816(acc[nt], ah0, ah1, ah2, ah3, bh0, bh1);
                mma16816(acc[nt], al0, al1, al2, al3, bh0, bh1);
                mma16816(acc[nt], ah0, ah1, ah2, ah3, bl0, bl1);
            }
        }

        int nodeLo = m0 + egrp * 16 + (lane >> 2);
        int jbase = n0 + jgrp * 128 + (lane & 3) * 2;
        #pragma unroll
        for (int nt = 0; nt < 16; nt++) {
            if (nodeLo < N_NODES)
                *(float2*)&g_P[(size_t)nodeLo * 512 + jbase + nt * 8] =
                    make_float2(acc[nt][0], acc[nt][1]);
            if (nodeLo + 8 < N_NODES)
                *(float2*)&g_P[(size_t)(nodeLo + 8) * 512 + jbase + nt * 8] =
                    make_float2(acc[nt][2], acc[nt][3]);
        }
        __syncthreads();
    }
}

// ---------------------------------------------------------------------------
// Edge kernel: B HOISTED INTO REGISTERS (loop-invariant We fragments).
// Block = 256 thr (8 warps), tile = 64 edges x 128 j (jhalf = blockIdx.y picks
// matched val dims [64h,64h+64) + mul dims [128+64h,...)).
// Warp = 32 edges (egrp=wid>>2) x 32 j (jgrp=wid&3). B frags: 64 regs, loaded
// once via ldmatrix in prologue -> ZERO B SMEM reads in the main loop.
// Epilogue: half-warp-per-edge coalesced P gathers + red.v4 scatter.
// ---------------------------------------------------------------------------
#define ESTR 72
#define EB_H 0                       // prologue only: 128*72*2 = 18432
#define EB_L 18432                   // prologue only: 18432 (ends 36864)
#define EA_H 0                       // main loop: 64*72*2 = 9216 (reuses EB_H)
#define EA_L 9216                    // ends 18432
#define E_STG 18432                  // 64 * 132 * 4 = 33792 (reuses EB_L) -> 52224
#define E_IDX 52224                  // 128 ints -> 52736
#define EDGE_SMEM 52736

__global__ __launch_bounds__(256, 2) void edge_kernel(
    const float* __restrict__ ef, const int* __restrict__ ei,
    const float* __restrict__ b_val, const float* __restrict__ b_mul,
    float* __restrict__ out)
{
    extern __shared__ char smem[];
    u32 sb = smem_u32(smem);
    int tid = threadIdx.x, wid = tid >> 5, lane = tid & 31;
    int jhalf = blockIdx.y;            // 0 or 1: dims [64*jhalf, 64*jhalf+64)
    float* stgf = (float*)(smem + E_STG);
    int* s_sh = (int*)(smem + E_IDX);
    int* r_sh = s_sh + 64;

    // ---- Prologue: load B slice [128 local j][64 k] hi/lo to smem ----
    // local j: 0..63 = val rows (global jhalf*64 + jl), 64..127 = mul rows
    // (global 128 + jhalf*64 + (jl-64)).
    {
        int jl = tid >> 1, k0 = (tid & 1) * 32;
        int jg = (jl < 64) ? (jhalf * 64 + jl) : (128 + jhalf * 64 + (jl - 64));
        #pragma unroll
        for (int c = 0; c < 32; c += 2) {
            __nv_bfloat162 h2, l2;
            h2.x = g_WeH[jg * 64 + k0 + c]; h2.y = g_WeH[jg * 64 + k0 + c + 1];
            l2.x = g_WeL[jg * 64 + k0 + c]; l2.y = g_WeL[jg * 64 + k0 + c + 1];
            *(__nv_bfloat162*)(smem + EB_H + (jl * ESTR + k0 + c) * 2) = h2;
            *(__nv_bfloat162*)(smem + EB_L + (jl * ESTR + k0 + c) * 2) = l2;
        }
    }
    __syncthreads();

    // ---- ldmatrix B fragments into registers (held for whole kernel) ----
    int egrp = wid >> 2, jgrp = wid & 3;          // egrp: 0..1, jgrp: 0..3
    u32 bregH[4][4][2], bregL[4][4][2];           // [kk][nt][reg]
    {
        u32 bBH = sb + EB_H + ((jgrp * 32 + ((lane >> 4) & 1) * 8 + (lane & 7)) * ESTR
                               + ((lane >> 3) & 1) * 8) * 2;
        u32 bBL = bBH + (EB_L - EB_H);
        #pragma unroll
        for (int kk = 0; kk < 4; kk++) {
            #pragma unroll
            for (int np = 0; np < 2; np++) {
                u32 r0, r1, r2, r3;
                ldsm4(bBH + np * (16 * ESTR * 2) + kk * 32, r0, r1, r2, r3);
                bregH[kk][np * 2 + 0][0] = r0; bregH[kk][np * 2 + 0][1] = r1;
                bregH[kk][np * 2 + 1][0] = r2; bregH[kk][np * 2 + 1][1] = r3;
                ldsm4(bBL + np * (16 * ESTR * 2) + kk * 32, r0, r1, r2, r3);
                bregL[kk][np * 2 + 0][0] = r0; bregL[kk][np * 2 + 0][1] = r1;
                bregL[kk][np * 2 + 1][0] = r2; bregL[kk][np * 2 + 1][1] = r3;
            }
        }
    }
    __syncthreads();   // B smem consumed; regions reused below

    const float4 bv4 = *(const float4*)&b_val[jhalf * 64 + (lane & 15) * 4];
    const float4 bm4 = *(const float4*)&b_mul[jhalf * 64 + (lane & 15) * 4];

    u32 aHb = sb + EA_H + ((lane & 15) * ESTR + (lane >> 4) * 8) * 2;
    u32 aLb = aHb + (EA_L - EA_H);

    const int ntiles = N_EDGES / 64;   // 12500
    for (int tile = blockIdx.x; tile < ntiles; tile += gridDim.x) {
        int e0 = tile * 64;
        if (tid < 64)       s_sh[tid] = ei[e0 + tid];
        else if (tid < 128) r_sh[tid - 64] = ei[N_EDGES + e0 + tid - 64];

        // fill A (ef tile [64][64]) hi/lo
        {
            int e = tid >> 2, k0 = (tid & 3) * 16;
            const float2* src = (const float2*)&ef[(size_t)(e0 + e) * ED + k0];
            #pragma unroll
            for (int c = 0; c < 16; c += 2) {
                float2 xv = src[c >> 1];
                __nv_bfloat16 h0, l0, h1, l1;
                split_bf16(xv.x, h0, l0); split_bf16(xv.y, h1, l1);
                *(__nv_bfloat162*)(smem + EA_H + (e * ESTR + k0 + c) * 2) = __nv_bfloat162(h0, h1);
                *(__nv_bfloat162*)(smem + EA_L + (e * ESTR + k0 + c) * 2) = __nv_bfloat162(l0, l1);
            }
        }
        __syncthreads();

        float acc[2][4][4];
        #pragma unroll
        for (int mt = 0; mt < 2; mt++)
            #pragma unroll
            for (int nt = 0; nt < 4; nt++)
                #pragma unroll
                for (int j = 0; j < 4; j++) acc[mt][nt][j] = 0.f;

        #pragma unroll
        for (int mt = 0; mt < 2; mt++) {
            u32 aOff = (u32)((egrp * 32 + mt * 16) * ESTR * 2);
            #pragma unroll
            for (int kk = 0; kk < 4; kk++) {
                u32 ah0, ah1, ah2, ah3, al0, al1, al2, al3;
                ldsm4(aHb + aOff + kk * 32, ah0, ah1, ah2, ah3);
                ldsm4(aLb + aOff + kk * 32, al0, al1, al2, al3);
                #pragma unroll
                for (int nt = 0; nt < 4; nt++) {
                    mma16816(acc[mt][nt], ah0, ah1, ah2, ah3,
                             bregH[kk][nt][0], bregH[kk][nt][1]);
                    mma16816(acc[mt][nt], al0, al1, al2, al3,
                             bregH[kk][nt][0], bregH[kk][nt][1]);
                    mma16816(acc[mt][nt], ah0, ah1, ah2, ah3,
                             bregL[kk][nt][0], bregL[kk][nt][1]);
                }
            }
        }

        // stage D [64 e][128 j] -> smem (row stride 132 floats)
        #pragma unroll
        for (int mt = 0; mt < 2; mt++) {
            int eLo = egrp * 32 + mt * 16 + (lane >> 2);
            int jb = jgrp * 32 + (lane & 3) * 2;
            #pragma unroll
            for (int nt = 0; nt < 4; nt++) {
                *(float2*)&stgf[eLo * 132 + jb + nt * 8] =
                    make_float2(acc[mt][nt][0], acc[mt][nt][1]);
                *(float2*)&stgf[(eLo + 8) * 132 + jb + nt * 8] =
                    make_float2(acc[mt][nt][2], acc[mt][nt][3]);
            }
        }
        __syncthreads();

        // epilogue: half-warp-per-edge; lanes 0-15 edge eA, 16-31 edge eB.
        // sub = lane&15 owns dims jhalf*64 + sub*4 .. +3.
        #pragma unroll 1
        for (int it = 0; it < 4; it++) {
            int e = it * 16 + (lane >> 4) * 8 + wid;
            int sub = lane & 15;
            float4 dv = *(const float4*)&stgf[e * 132 + sub * 4];
            float4 dm = *(const float4*)&stgf[e * 132 + 64 + sub * 4];
            int s = s_sh[e];
            int r = r_sh[e];
            int dbase = jhalf * 64 + sub * 4;
            const float4 psv = *(const float4*)&g_P[(size_t)s * 512 + dbase];
            const float4 prv = *(const float4*)&g_P[(size_t)r * 512 + 128 + dbase];
            const float4 psm = *(const float4*)&g_P[(size_t)s * 512 + 256 + dbase];
            const float4 prm = *(const float4*)&g_P[(size_t)r * 512 + 384 + dbase];

            float v0 = dv.x + psv.x + prv.x + bv4.x;
            float v1 = dv.y + psv.y + prv.y + bv4.y;
            float v2 = dv.z + psv.z + prv.z + bv4.z;
            float v3 = dv.w + psv.w + prv.w + bv4.w;
            float m0 = dm.x + psm.x + prm.x + bm4.x;
            float m1 = dm.y + psm.y + prm.y + bm4.y;
            float m2 = dm.z + psm.z + prm.z + bm4.z;
            float m3 = dm.w + psm.w + prm.w + bm4.w;

            float g0 = softplus_f(v0) * sigmoid_f(m0);
            float g1 = softplus_f(v1) * sigmoid_f(m1);
            float g2 = softplus_f(v2) * sigmoid_f(m2);
            float g3 = softplus_f(v3) * sigmoid_f(m3);

            red4(out + (size_t)r * ND + dbase, g0, g1, g2, g3);
        }
        __syncthreads();
    }
}

// ---------------------------------------------------------------------------
extern "C" void kernel_launch(void* const* d_in, const int* in_sizes, int n_in,
                              void* d_out, int out_size) {
    const float* x  = (const float*)d_in[0];
    const int*   ei = (const int*)  d_in[1];
    const float* ef = (const float*)d_in[2];
    const float* Wv = (const float*)d_in[3];
    const float* bv = (const float*)d_in[4];
    const float* Wm = (const float*)d_in[5];
    const float* bm = (const float*)d_in[6];
    float* out = (float*)d_out;

    cudaFuncSetAttribute(node_gemm_kernel,
                         cudaFuncAttributeMaxDynamicSharedMemorySize, NODE_SMEM);
    cudaFuncSetAttribute(edge_kernel,
                         cudaFuncAttributeMaxDynamicSharedMemorySize, EDGE_SMEM);

    pack_weights_kernel<<<256, 256>>>(Wv, Wm);

    int n4 = N_NODES * ND / 4;
    zero_out_kernel<<<(n4 + 255) / 256, 256>>>((float4*)out, n4);

    node_gemm_kernel<<<dim3(74, 2), 512, NODE_SMEM>>>(x);

    edge_kernel<<<dim3(148, 2), 256, EDGE_SMEM>>>(ef, ei, bv, bm, out);
}

// round 8
// speedup vs baseline: 1.2910x; 1.0904x over previous
#include <cuda_runtime.h>
#include <cuda_bf16.h>
#include <stdint.h>

#define N_NODES 50000
#define N_EDGES 800000
#define ND 128
#define ED 64
#define HID 320

typedef uint32_t u32;

// ---------------- device globals (allocation-guard safe) -------------------
__device__ float g_P[(size_t)N_NODES * 512];     // node projections [N,512] fp32
__device__ __nv_bfloat16 g_WnH[512 * 128];       // node weights hi  [j][k]
__device__ __nv_bfloat16 g_WnL[512 * 128];       // node weights lo
__device__ __nv_bfloat16 g_WeH[256 * 64];        // edge weights hi  [j][k]
__device__ __nv_bfloat16 g_WeL[256 * 64];        // edge weights lo

// ---------------- helpers ----------------------------------------------------
__device__ __forceinline__ u32 smem_u32(const void* p) {
    u32 a;
    asm("{ .reg .u64 t; cvta.to.shared.u64 t, %1; cvt.u32.u64 %0, t; }" : "=r"(a) : "l"(p));
    return a;
}
__device__ __forceinline__ void ldsm4(u32 addr, u32& r0, u32& r1, u32& r2, u32& r3) {
    asm volatile("ldmatrix.sync.aligned.m8n8.x4.shared.b16 {%0,%1,%2,%3}, [%4];"
                 : "=r"(r0), "=r"(r1), "=r"(r2), "=r"(r3) : "r"(addr));
}
__device__ __forceinline__ void ldsm2(u32 addr, u32& r0, u32& r1) {
    asm volatile("ldmatrix.sync.aligned.m8n8.x2.shared.b16 {%0,%1}, [%2];"
                 : "=r"(r0), "=r"(r1) : "r"(addr));
}
__device__ __forceinline__ void mma16816(float* d, u32 a0, u32 a1, u32 a2, u32 a3,
                                         u32 b0, u32 b1) {
    asm volatile(
        "mma.sync.aligned.m16n8k16.row.col.f32.bf16.bf16.f32 "
        "{%0,%1,%2,%3}, {%4,%5,%6,%7}, {%8,%9}, {%0,%1,%2,%3};"
        : "+f"(d[0]), "+f"(d[1]), "+f"(d[2]), "+f"(d[3])
        : "r"(a0), "r"(a1), "r"(a2), "r"(a3), "r"(b0), "r"(b1));
}
__device__ __forceinline__ void red4(float* p, float a, float b, float c, float d) {
    asm volatile("red.global.add.v4.f32 [%0], {%1,%2,%3,%4};"
                 :: "l"(p), "f"(a), "f"(b), "f"(c), "f"(d) : "memory");
}
__device__ __forceinline__ void split_bf16(float v, __nv_bfloat16& h, __nv_bfloat16& l) {
    h = __float2bfloat16_rn(v);
    l = __float2bfloat16_rn(v - __bfloat162float(h));
}
__device__ __forceinline__ float softplus_f(float x) {
    return fmaxf(x, 0.f) + __logf(1.f + __expf(-fabsf(x)));
}
__device__ __forceinline__ float sigmoid_f(float x) {
    return __fdividef(1.f, 1.f + __expf(-x));
}

// ---------------------------------------------------------------------------
// pack: bf16 hi/lo weights with column permutation
// ---------------------------------------------------------------------------
__global__ void pack_weights_kernel(const float* __restrict__ Wv,
                                    const float* __restrict__ Wm) {
    int i = blockIdx.x * blockDim.x + threadIdx.x;
    if (i < 512 * 128) {
        int j = i >> 7, k = i & 127;
        float v;
        if (j < 128)      v = Wv[j * HID + k];
        else if (j < 256) v = Wv[(j - 128) * HID + 128 + k];
        else if (j < 384) v = Wm[(j - 256) * HID + k];
        else              v = Wm[(j - 384) * HID + 128 + k];
        __nv_bfloat16 h, l; split_bf16(v, h, l);
        g_WnH[i] = h; g_WnL[i] = l;
    }
    if (i < 256 * 64) {
        int j = i >> 6, k = i & 63;
        float v = (j < 128) ? Wv[j * HID + 256 + k] : Wm[(j - 128) * HID + 256 + k];
        __nv_bfloat16 h, l; split_bf16(v, h, l);
        g_WeH[i] = h; g_WeL[i] = l;
    }
}

__global__ void zero_out_kernel(float4* __restrict__ out, int n4) {
    int i = blockIdx.x * blockDim.x + threadIdx.x;
    if (i < n4) out[i] = make_float4(0.f, 0.f, 0.f, 0.f);
}

// ---------------------------------------------------------------------------
// Node GEMM (HMMA bf16x3) — R4 configuration (known good):
// tile 128 nodes x 256 j, 512 thr = 16 warps, warp = 16n x 128j.
// ---------------------------------------------------------------------------
#define NSTR 136
#define N_BH 0
#define N_BL 69632
#define N_AH 139264
#define N_AL 174080
#define NODE_SMEM 208896

__global__ __launch_bounds__(512, 1) void node_gemm_kernel(const float* __restrict__ X) {
    extern __shared__ char smem[];
    u32 sb = smem_u32(smem);
    int tid = threadIdx.x, wid = tid >> 5, lane = tid & 31;
    int n0 = blockIdx.y * 256;

    {
        int j = tid >> 1, k0 = (tid & 1) * 64;
        #pragma unroll
        for (int c = 0; c < 64; c += 2) {
            __nv_bfloat162 h2, l2;
            h2.x = g_WnH[(n0 + j) * 128 + k0 + c];
            h2.y = g_WnH[(n0 + j) * 128 + k0 + c + 1];
            l2.x = g_WnL[(n0 + j) * 128 + k0 + c];
            l2.y = g_WnL[(n0 + j) * 128 + k0 + c + 1];
            *(__nv_bfloat162*)(smem + N_BH + (j * NSTR + k0 + c) * 2) = h2;
            *(__nv_bfloat162*)(smem + N_BL + (j * NSTR + k0 + c) * 2) = l2;
        }
    }

    int egrp = wid >> 1, jgrp = wid & 1;
    u32 aH = sb + N_AH + ((egrp * 16 + (lane & 15)) * NSTR + (lane >> 4) * 8) * 2;
    u32 aL = sb + N_AL + ((egrp * 16 + (lane & 15)) * NSTR + (lane >> 4) * 8) * 2;
    u32 bH = sb + N_BH + ((jgrp * 128 + (lane & 7)) * NSTR + (lane & 8)) * 2;
    u32 bL = sb + N_BL + ((jgrp * 128 + (lane & 7)) * NSTR + (lane & 8)) * 2;

    const int ntiles = (N_NODES + 127) / 128;   // 391
    for (int t = blockIdx.x; t < ntiles; t += gridDim.x) {
        int m0 = t * 128;
        {
            int row = tid >> 2, k0 = (tid & 3) * 32;
            int gm = m0 + row;
            #pragma unroll
            for (int c = 0; c < 32; c += 2) {
                float2 xv = make_float2(0.f, 0.f);
                if (gm < N_NODES) xv = *(const float2*)&X[(size_t)gm * ND + k0 + c];
                __nv_bfloat16 h0, l0, h1, l1;
                split_bf16(xv.x, h0, l0); split_bf16(xv.y, h1, l1);
                *(__nv_bfloat162*)(smem + N_AH + (row * NSTR + k0 + c) * 2) = __nv_bfloat162(h0, h1);
                *(__nv_bfloat162*)(smem + N_AL + (row * NSTR + k0 + c) * 2) = __nv_bfloat162(l0, l1);
            }
        }
        __syncthreads();

        float acc[16][4];
        #pragma unroll
        for (int i = 0; i < 16; i++)
            #pragma unroll
            for (int j = 0; j < 4; j++) acc[i][j] = 0.f;

        #pragma unroll
        for (int kk = 0; kk < 8; kk++) {
            u32 ah0, ah1, ah2, ah3, al0, al1, al2, al3;
            ldsm4(aH + kk * 32, ah0, ah1, ah2, ah3);
            ldsm4(aL + kk * 32, al0, al1, al2, al3);
            #pragma unroll
            for (int nt = 0; nt < 16; nt++) {
                u32 bh0, bh1, bl0, bl1;
                ldsm2(bH + nt * (8 * NSTR * 2) + kk * 32, bh0, bh1);
                ldsm2(bL + nt * (8 * NSTR * 2) + kk * 32, bl0, bl1);
                mma16816(acc[nt], ah0, ah1, ah2, ah3, bh0, bh1);
                mma16816(acc[nt], al0, al1, al2, al3, bh0, bh1);
                mma16816(acc[nt], ah0, ah1, ah2, ah3, bl0, bl1);
            }
        }

        int nodeLo = m0 + egrp * 16 + (lane >> 2);
        int jbase = n0 + jgrp * 128 + (lane & 3) * 2;
        #pragma unroll
        for (int nt = 0; nt < 16; nt++) {
            if (nodeLo < N_NODES)
                *(float2*)&g_P[(size_t)nodeLo * 512 + jbase + nt * 8] =
                    make_float2(acc[nt][0], acc[nt][1]);
            if (nodeLo + 8 < N_NODES)
                *(float2*)&g_P[(size_t)(nodeLo + 8) * 512 + jbase + nt * 8] =
                    make_float2(acc[nt][2], acc[nt][3]);
        }
        __syncthreads();
    }
}

// ---------------------------------------------------------------------------
// Edge kernel v7: STAGING-FREE epilogue via matched val/mul fragment layout.
// Block 256 thr / 8 warps, 3 CTAs/SM. Tile = 64 edges x 128 j (jhalf block
// class picks dims [64h, 64h+64)). Warp = 32 edges x 32 j where its n-slice
// rows are PERMUTED so nt 0,1 hold 16 val dims and nt 2,3 the SAME 16 mul
// dims, interleaved so each lane's fragments cover 4 CONSECUTIVE output dims.
// Epilogue runs entirely in accumulator registers: float4 P gathers + red.v4.
// B/A in xor-swizzled 128B rows (no padding, conflict-free ldmatrix).
// ---------------------------------------------------------------------------
#define EB_H 0                      // 128 rows * 128B = 16384
#define EB_L 16384                  // -> 32768
#define EA_H 32768                  // 64 rows * 128B = 8192
#define EA_L 40960                  // -> 49152
#define E_IDX 49152                 // 128 ints -> 49664
#define EDGE_SMEM 49664

__global__ __launch_bounds__(256, 3) void edge_kernel(
    const float* __restrict__ ef, const int* __restrict__ ei,
    const float* __restrict__ b_val, const float* __restrict__ b_mul,
    float* __restrict__ out)
{
    extern __shared__ char smem[];
    u32 sb = smem_u32(smem);
    int tid = threadIdx.x, wid = tid >> 5, lane = tid & 31;
    int jhalf = blockIdx.y;
    int* s_sh = (int*)(smem + E_IDX);
    int* r_sh = s_sh + 64;

    // ---- B fill (once): permuted rows, xor-swizzled ----
    // local row jl = jgrp*32 + ntb*8 + rr ; ntb 0,1 = val, 2,3 = mul.
    // dim-within-16 dd = (rr>>1)*4 + (ntb&1)*2 + (rr&1)  -> lane q=rr>>1 owns
    // 4 consecutive dims q*4..q*4+3 across (ntb, bit).
    {
        int jl = tid >> 1, k0 = (tid & 1) * 32;
        int jgrp_ = jl >> 5, jj = jl & 31, ntb = jj >> 3, rr = jj & 7;
        int dd = (rr >> 1) * 4 + (ntb & 1) * 2 + (rr & 1);
        int jg = ((ntb < 2) ? 0 : 128) + jhalf * 64 + jgrp_ * 16 + dd;
        int xorm = (jl & 7) << 4;
        #pragma unroll
        for (int c = 0; c < 32; c += 2) {
            u32 off = (u32)(jl * 128) + (u32)(((k0 + c) * 2) ^ xorm);
            __nv_bfloat162 h2, l2;
            h2.x = g_WeH[jg * 64 + k0 + c]; h2.y = g_WeH[jg * 64 + k0 + c + 1];
            l2.x = g_WeL[jg * 64 + k0 + c]; l2.y = g_WeL[jg * 64 + k0 + c + 1];
            *(__nv_bfloat162*)(smem + EB_H + off) = h2;
            *(__nv_bfloat162*)(smem + EB_L + off) = l2;
        }
    }
    __syncthreads();

    int egrp = wid >> 2, jgrp = wid & 3;   // egrp 0..1 (32 edges), jgrp 0..3 (16 dims)

    // B fragment addressing (R5-verified mapping + swizzle)
    int jrow = jgrp * 32 + ((lane >> 4) & 1) * 8 + (lane & 7);
    u32 bHrow = sb + EB_H + (u32)(jrow * 128);
    int bxor = (jrow & 7) << 4;
    int bk16 = ((lane >> 3) & 1) * 16;

    // A fragment addressing
    u32 aHrow = sb + EA_H + (u32)((lane & 15) * 128);
    int axor = (lane & 7) << 4;
    int ak16 = (lane >> 4) * 16;

    int q = lane & 3;
    int dbase = jhalf * 64 + jgrp * 16 + q * 4;
    const float4 bv4 = *(const float4*)&b_val[dbase];
    const float4 bm4 = *(const float4*)&b_mul[dbase];

    const int ntiles = N_EDGES / 64;   // 12500
    for (int tile = blockIdx.x; tile < ntiles; tile += gridDim.x) {
        int e0 = tile * 64;
        if (tid < 64)       s_sh[tid] = ei[e0 + tid];
        else if (tid < 128) r_sh[tid - 64] = ei[N_EDGES + e0 + tid - 64];

        // A fill (ef tile [64 e][64 k]) hi/lo, swizzled 128B rows
        {
            int e = tid >> 2, k0 = (tid & 3) * 16;
            int xm = (e & 7) << 4;
            const float2* src = (const float2*)&ef[(size_t)(e0 + e) * ED + k0];
            #pragma unroll
            for (int c = 0; c < 16; c += 2) {
                float2 xv = src[c >> 1];
                __nv_bfloat16 h0, l0, h1, l1;
                split_bf16(xv.x, h0, l0); split_bf16(xv.y, h1, l1);
                u32 off = (u32)(e * 128) + (u32)(((k0 + c) * 2) ^ xm);
                *(__nv_bfloat162*)(smem + EA_H + off) = __nv_bfloat162(h0, h1);
                *(__nv_bfloat162*)(smem + EA_L + off) = __nv_bfloat162(l0, l1);
            }
        }
        __syncthreads();

        float acc[2][4][4];
        #pragma unroll
        for (int mt = 0; mt < 2; mt++)
            #pragma unroll
            for (int nt = 0; nt < 4; nt++)
                #pragma unroll
                for (int j = 0; j < 4; j++) acc[mt][nt][j] = 0.f;

        #pragma unroll
        for (int mt = 0; mt < 2; mt++) {
            u32 aBase = aHrow + (u32)((egrp * 32 + mt * 16) * 128);
            #pragma unroll
            for (int kk = 0; kk < 4; kk++) {
                u32 akx = (u32)((kk * 32 + ak16) ^ axor);
                u32 ah0, ah1, ah2, ah3, al0, al1, al2, al3;
                ldsm4(aBase + akx, ah0, ah1, ah2, ah3);
                ldsm4(aBase + (EA_L - EA_H) + akx, al0, al1, al2, al3);
                u32 bkx = (u32)((kk * 32 + bk16) ^ bxor);
                #pragma unroll
                for (int np = 0; np < 2; np++) {
                    u32 bh0, bh1, bh2, bh3, bl0, bl1, bl2, bl3;
                    ldsm4(bHrow + np * 2048 + bkx, bh0, bh1, bh2, bh3);
                    ldsm4(bHrow + (EB_L - EB_H) + np * 2048 + bkx, bl0, bl1, bl2, bl3);
                    mma16816(acc[mt][np * 2 + 0], ah0, ah1, ah2, ah3, bh0, bh1);
                    mma16816(acc[mt][np * 2 + 0], al0, al1, al2, al3, bh0, bh1);
                    mma16816(acc[mt][np * 2 + 0], ah0, ah1, ah2, ah3, bl0, bl1);
                    mma16816(acc[mt][np * 2 + 1], ah0, ah1, ah2, ah3, bh2, bh3);
                    mma16816(acc[mt][np * 2 + 1], al0, al1, al2, al3, bh2, bh3);
                    mma16816(acc[mt][np * 2 + 1], ah0, ah1, ah2, ah3, bl2, bl3);
                }
            }
        }

        // ---- register epilogue (no staging) ----
        // lane holds dims dbase..dbase+3: val = acc[mt][0..1], mul = acc[mt][2..3];
        // within nt, c = 2h+bit selects edge row h and dim bit.
        #pragma unroll
        for (int mt = 0; mt < 2; mt++) {
            #pragma unroll
            for (int h = 0; h < 2; h++) {
                int e = egrp * 32 + mt * 16 + h * 8 + (lane >> 2);
                int s = s_sh[e];
                int r = r_sh[e];
                const float4 psv = *(const float4*)&g_P[(size_t)s * 512 + dbase];
                const float4 prv = *(const float4*)&g_P[(size_t)r * 512 + 128 + dbase];
                const float4 psm = *(const float4*)&g_P[(size_t)s * 512 + 256 + dbase];
                const float4 prm = *(const float4*)&g_P[(size_t)r * 512 + 384 + dbase];

                float v0 = acc[mt][0][2 * h + 0] + psv.x + prv.x + bv4.x;
                float v1 = acc[mt][0][2 * h + 1] + psv.y + prv.y + bv4.y;
                float v2 = acc[mt][1][2 * h + 0] + psv.z + prv.z + bv4.z;
                float v3 = acc[mt][1][2 * h + 1] + psv.w + prv.w + bv4.w;
                float m0 = acc[mt][2][2 * h + 0] + psm.x + prm.x + bm4.x;
                float m1 = acc[mt][2][2 * h + 1] + psm.y + prm.y + bm4.y;
                float m2 = acc[mt][3][2 * h + 0] + psm.z + prm.z + bm4.z;
                float m3 = acc[mt][3][2 * h + 1] + psm.w + prm.w + bm4.w;

                float g0 = softplus_f(v0) * sigmoid_f(m0);
                float g1 = softplus_f(v1) * sigmoid_f(m1);
                float g2 = softplus_f(v2) * sigmoid_f(m2);
                float g3 = softplus_f(v3) * sigmoid_f(m3);

                red4(out + (size_t)r * ND + dbase, g0, g1, g2, g3);
            }
        }
        __syncthreads();   // protect A/idx before next tile's fill
    }
}

// ---------------------------------------------------------------------------
extern "C" void kernel_launch(void* const* d_in, const int* in_sizes, int n_in,
                              void* d_out, int out_size) {
    const float* x  = (const float*)d_in[0];
    const int*   ei = (const int*)  d_in[1];
    const float* ef = (const float*)d_in[2];
    const float* Wv = (const float*)d_in[3];
    const float* bv = (const float*)d_in[4];
    const float* Wm = (const float*)d_in[5];
    const float* bm = (const float*)d_in[6];
    float* out = (float*)d_out;

    cudaFuncSetAttribute(node_gemm_kernel,
                         cudaFuncAttributeMaxDynamicSharedMemorySize, NODE_SMEM);
    cudaFuncSetAttribute(edge_kernel,
                         cudaFuncAttributeMaxDynamicSharedMemorySize, EDGE_SMEM);

    pack_weights_kernel<<<256, 256>>>(Wv, Wm);

    int n4 = N_NODES * ND / 4;
    zero_out_kernel<<<(n4 + 255) / 256, 256>>>((float4*)out, n4);

    node_gemm_kernel<<<dim3(74, 2), 512, NODE_SMEM>>>(x);

    edge_kernel<<<dim3(222, 2), 256, EDGE_SMEM>>>(ef, ei, bv, bm, out);
}

// round 9
// speedup vs baseline: 1.5211x; 1.1783x over previous
#include <cuda_runtime.h>
#include <cuda_bf16.h>
#include <cuda_fp16.h>
#include <stdint.h>

#define N_NODES 50000
#define N_EDGES 800000
#define ND 128
#define ED 64
#define HID 320

typedef uint32_t u32;

// ---------------- device globals (allocation-guard safe) -------------------
__device__ __half g_Ph[(size_t)N_NODES * 512];   // node projections [N,512] fp16
__device__ __nv_bfloat16 g_WnH[512 * 128];       // node weights hi [j][k] (bf16x3)
__device__ __nv_bfloat16 g_WnL[512 * 128];       // node weights lo
__device__ __half g_WeH[256 * 64];               // edge weights hi [j][k] (fp16x2)
__device__ __half g_WeL[256 * 64];               // edge weights lo

// ---------------- helpers ----------------------------------------------------
__device__ __forceinline__ u32 smem_u32(const void* p) {
    u32 a;
    asm("{ .reg .u64 t; cvta.to.shared.u64 t, %1; cvt.u32.u64 %0, t; }" : "=r"(a) : "l"(p));
    return a;
}
__device__ __forceinline__ void ldsm4(u32 addr, u32& r0, u32& r1, u32& r2, u32& r3) {
    asm volatile("ldmatrix.sync.aligned.m8n8.x4.shared.b16 {%0,%1,%2,%3}, [%4];"
                 : "=r"(r0), "=r"(r1), "=r"(r2), "=r"(r3) : "r"(addr));
}
__device__ __forceinline__ void ldsm2(u32 addr, u32& r0, u32& r1) {
    asm volatile("ldmatrix.sync.aligned.m8n8.x2.shared.b16 {%0,%1}, [%2];"
                 : "=r"(r0), "=r"(r1) : "r"(addr));
}
// bf16 MMA (node kernel)
__device__ __forceinline__ void mma16816(float* d, u32 a0, u32 a1, u32 a2, u32 a3,
                                         u32 b0, u32 b1) {
    asm volatile(
        "mma.sync.aligned.m16n8k16.row.col.f32.bf16.bf16.f32 "
        "{%0,%1,%2,%3}, {%4,%5,%6,%7}, {%8,%9}, {%0,%1,%2,%3};"
        : "+f"(d[0]), "+f"(d[1]), "+f"(d[2]), "+f"(d[3])
        : "r"(a0), "r"(a1), "r"(a2), "r"(a3), "r"(b0), "r"(b1));
}
// fp16 MMA (edge kernel)
__device__ __forceinline__ void mma16816h(float* d, u32 a0, u32 a1, u32 a2, u32 a3,
                                          u32 b0, u32 b1) {
    asm volatile(
        "mma.sync.aligned.m16n8k16.row.col.f32.f16.f16.f32 "
        "{%0,%1,%2,%3}, {%4,%5,%6,%7}, {%8,%9}, {%0,%1,%2,%3};"
        : "+f"(d[0]), "+f"(d[1]), "+f"(d[2]), "+f"(d[3])
        : "r"(a0), "r"(a1), "r"(a2), "r"(a3), "r"(b0), "r"(b1));
}
__device__ __forceinline__ void red4(float* p, float a, float b, float c, float d) {
    asm volatile("red.global.add.v4.f32 [%0], {%1,%2,%3,%4};"
                 :: "l"(p), "f"(a), "f"(b), "f"(c), "f"(d) : "memory");
}
__device__ __forceinline__ void split_bf16(float v, __nv_bfloat16& h, __nv_bfloat16& l) {
    h = __float2bfloat16_rn(v);
    l = __float2bfloat16_rn(v - __bfloat162float(h));
}
__device__ __forceinline__ void split_f16(float v, __half& h, __half& l) {
    h = __float2half_rn(v);
    l = __float2half_rn(v - __half2float(h));
}
__device__ __forceinline__ float softplus_f(float x) {
    return fmaxf(x, 0.f) + __logf(1.f + __expf(-fabsf(x)));
}
__device__ __forceinline__ float sigmoid_f(float x) {
    return __fdividef(1.f, 1.f + __expf(-x));
}
// gather 4 consecutive fp16 P dims -> float4
__device__ __forceinline__ float4 gather4h(const __half* p) {
    uint2 u = *(const uint2*)p;
    __half2 h01 = *(__half2*)&u.x;
    __half2 h23 = *(__half2*)&u.y;
    float2 f01 = __half22float2(h01);
    float2 f23 = __half22float2(h23);
    return make_float4(f01.x, f01.y, f23.x, f23.y);
}

// ---------------------------------------------------------------------------
// pack weights
// ---------------------------------------------------------------------------
__global__ void pack_weights_kernel(const float* __restrict__ Wv,
                                    const float* __restrict__ Wm) {
    int i = blockIdx.x * blockDim.x + threadIdx.x;
    if (i < 512 * 128) {
        int j = i >> 7, k = i & 127;
        float v;
        if (j < 128)      v = Wv[j * HID + k];
        else if (j < 256) v = Wv[(j - 128) * HID + 128 + k];
        else if (j < 384) v = Wm[(j - 256) * HID + k];
        else              v = Wm[(j - 384) * HID + 128 + k];
        __nv_bfloat16 h, l; split_bf16(v, h, l);
        g_WnH[i] = h; g_WnL[i] = l;
    }
    if (i < 256 * 64) {
        int j = i >> 6, k = i & 63;
        float v = (j < 128) ? Wv[j * HID + 256 + k] : Wm[(j - 128) * HID + 256 + k];
        __half h, l; split_f16(v, h, l);
        g_WeH[i] = h; g_WeL[i] = l;
    }
}

__global__ void zero_out_kernel(float4* __restrict__ out, int n4) {
    int i = blockIdx.x * blockDim.x + threadIdx.x;
    if (i < n4) out[i] = make_float4(0.f, 0.f, 0.f, 0.f);
}

// ---------------------------------------------------------------------------
// Node GEMM (HMMA bf16x3, R4 config): tile 128 nodes x 256 j, epilogue -> fp16 P
// ---------------------------------------------------------------------------
#define NSTR 136
#define N_BH 0
#define N_BL 69632
#define N_AH 139264
#define N_AL 174080
#define NODE_SMEM 208896

__global__ __launch_bounds__(512, 1) void node_gemm_kernel(const float* __restrict__ X) {
    extern __shared__ char smem[];
    u32 sb = smem_u32(smem);
    int tid = threadIdx.x, wid = tid >> 5, lane = tid & 31;
    int n0 = blockIdx.y * 256;

    {
        int j = tid >> 1, k0 = (tid & 1) * 64;
        #pragma unroll
        for (int c = 0; c < 64; c += 2) {
            __nv_bfloat162 h2, l2;
            h2.x = g_WnH[(n0 + j) * 128 + k0 + c];
            h2.y = g_WnH[(n0 + j) * 128 + k0 + c + 1];
            l2.x = g_WnL[(n0 + j) * 128 + k0 + c];
            l2.y = g_WnL[(n0 + j) * 128 + k0 + c + 1];
            *(__nv_bfloat162*)(smem + N_BH + (j * NSTR + k0 + c) * 2) = h2;
            *(__nv_bfloat162*)(smem + N_BL + (j * NSTR + k0 + c) * 2) = l2;
        }
    }

    int egrp = wid >> 1, jgrp = wid & 1;
    u32 aH = sb + N_AH + ((egrp * 16 + (lane & 15)) * NSTR + (lane >> 4) * 8) * 2;
    u32 aL = sb + N_AL + ((egrp * 16 + (lane & 15)) * NSTR + (lane >> 4) * 8) * 2;
    u32 bH = sb + N_BH + ((jgrp * 128 + (lane & 7)) * NSTR + (lane & 8)) * 2;
    u32 bL = sb + N_BL + ((jgrp * 128 + (lane & 7)) * NSTR + (lane & 8)) * 2;

    const int ntiles = (N_NODES + 127) / 128;   // 391
    for (int t = blockIdx.x; t < ntiles; t += gridDim.x) {
        int m0 = t * 128;
        {
            int row = tid >> 2, k0 = (tid & 3) * 32;
            int gm = m0 + row;
            #pragma unroll
            for (int c = 0; c < 32; c += 2) {
                float2 xv = make_float2(0.f, 0.f);
                if (gm < N_NODES) xv = *(const float2*)&X[(size_t)gm * ND + k0 + c];
                __nv_bfloat16 h0, l0, h1, l1;
                split_bf16(xv.x, h0, l0); split_bf16(xv.y, h1, l1);
                *(__nv_bfloat162*)(smem + N_AH + (row * NSTR + k0 + c) * 2) = __nv_bfloat162(h0, h1);
                *(__nv_bfloat162*)(smem + N_AL + (row * NSTR + k0 + c) * 2) = __nv_bfloat162(l0, l1);
            }
        }
        __syncthreads();

        float acc[16][4];
        #pragma unroll
        for (int i = 0; i < 16; i++)
            #pragma unroll
            for (int j = 0; j < 4; j++) acc[i][j] = 0.f;

        #pragma unroll
        for (int kk = 0; kk < 8; kk++) {
            u32 ah0, ah1, ah2, ah3, al0, al1, al2, al3;
            ldsm4(aH + kk * 32, ah0, ah1, ah2, ah3);
            ldsm4(aL + kk * 32, al0, al1, al2, al3);
            #pragma unroll
            for (int nt = 0; nt < 16; nt++) {
                u32 bh0, bh1, bl0, bl1;
                ldsm2(bH + nt * (8 * NSTR * 2) + kk * 32, bh0, bh1);
                ldsm2(bL + nt * (8 * NSTR * 2) + kk * 32, bl0, bl1);
                mma16816(acc[nt], ah0, ah1, ah2, ah3, bh0, bh1);
                mma16816(acc[nt], al0, al1, al2, al3, bh0, bh1);
                mma16816(acc[nt], ah0, ah1, ah2, ah3, bl0, bl1);
            }
        }

        int nodeLo = m0 + egrp * 16 + (lane >> 2);
        int jbase = n0 + jgrp * 128 + (lane & 3) * 2;
        #pragma unroll
        for (int nt = 0; nt < 16; nt++) {
            if (nodeLo < N_NODES)
                *(__half2*)&g_Ph[(size_t)nodeLo * 512 + jbase + nt * 8] =
                    __floats2half2_rn(acc[nt][0], acc[nt][1]);
            if (nodeLo + 8 < N_NODES)
                *(__half2*)&g_Ph[(size_t)(nodeLo + 8) * 512 + jbase + nt * 8] =
                    __floats2half2_rn(acc[nt][2], acc[nt][3]);
        }
        __syncthreads();
    }
}

// ---------------------------------------------------------------------------
// Edge kernel v8: fp16 2-term MMA (A=ef single fp16, B=We fp16 hi/lo),
// fp16 P gathers, staging-free register epilogue (R7 layout).
// Block 256 thr / 8 warps, 3 CTAs/SM. Tile 64 edges x 128 j (jhalf class).
// ---------------------------------------------------------------------------
#define EB_H 0                      // 128 rows * 128B = 16384
#define EB_L 16384                  // -> 32768
#define EA_  32768                  // 64 rows * 128B = 8192 -> 40960
#define E_IDX 40960                 // 128 ints -> 41472
#define EDGE_SMEM 41472

__global__ __launch_bounds__(256, 3) void edge_kernel(
    const float* __restrict__ ef, const int* __restrict__ ei,
    const float* __restrict__ b_val, const float* __restrict__ b_mul,
    float* __restrict__ out)
{
    extern __shared__ char smem[];
    u32 sb = smem_u32(smem);
    int tid = threadIdx.x, wid = tid >> 5, lane = tid & 31;
    int jhalf = blockIdx.y;
    int* s_sh = (int*)(smem + E_IDX);
    int* r_sh = s_sh + 64;

    // ---- B fill (once): permuted rows, xor-swizzled, fp16 hi/lo ----
    {
        int jl = tid >> 1, k0 = (tid & 1) * 32;
        int jgrp_ = jl >> 5, jj = jl & 31, ntb = jj >> 3, rr = jj & 7;
        int dd = (rr >> 1) * 4 + (ntb & 1) * 2 + (rr & 1);
        int jg = ((ntb < 2) ? 0 : 128) + jhalf * 64 + jgrp_ * 16 + dd;
        int xorm = (jl & 7) << 4;
        #pragma unroll
        for (int c = 0; c < 32; c += 2) {
            u32 off = (u32)(jl * 128) + (u32)(((k0 + c) * 2) ^ xorm);
            __half2 h2, l2;
            h2.x = g_WeH[jg * 64 + k0 + c]; h2.y = g_WeH[jg * 64 + k0 + c + 1];
            l2.x = g_WeL[jg * 64 + k0 + c]; l2.y = g_WeL[jg * 64 + k0 + c + 1];
            *(__half2*)(smem + EB_H + off) = h2;
            *(__half2*)(smem + EB_L + off) = l2;
        }
    }
    __syncthreads();

    int egrp = wid >> 2, jgrp = wid & 3;

    int jrow = jgrp * 32 + ((lane >> 4) & 1) * 8 + (lane & 7);
    u32 bHrow = sb + EB_H + (u32)(jrow * 128);
    int bxor = (jrow & 7) << 4;
    int bk16 = ((lane >> 3) & 1) * 16;

    u32 aRow = sb + EA_ + (u32)((lane & 15) * 128);
    int axor = (lane & 7) << 4;
    int ak16 = (lane >> 4) * 16;

    int q = lane & 3;
    int dbase = jhalf * 64 + jgrp * 16 + q * 4;
    const float4 bv4 = *(const float4*)&b_val[dbase];
    const float4 bm4 = *(const float4*)&b_mul[dbase];

    const int ntiles = N_EDGES / 64;   // 12500
    for (int tile = blockIdx.x; tile < ntiles; tile += gridDim.x) {
        int e0 = tile * 64;
        if (tid < 64)       s_sh[tid] = ei[e0 + tid];
        else if (tid < 128) r_sh[tid - 64] = ei[N_EDGES + e0 + tid - 64];

        // A fill: ef tile [64 e][64 k] -> single fp16, swizzled 128B rows
        {
            int e = tid >> 2, k0 = (tid & 3) * 16;
            int xm = (e & 7) << 4;
            const float2* src = (const float2*)&ef[(size_t)(e0 + e) * ED + k0];
            #pragma unroll
            for (int c = 0; c < 16; c += 2) {
                float2 xv = src[c >> 1];
                u32 off = (u32)(e * 128) + (u32)(((k0 + c) * 2) ^ xm);
                *(__half2*)(smem + EA_ + off) = __floats2half2_rn(xv.x, xv.y);
            }
        }
        __syncthreads();

        float acc[2][4][4];
        #pragma unroll
        for (int mt = 0; mt < 2; mt++)
            #pragma unroll
            for (int nt = 0; nt < 4; nt++)
                #pragma unroll
                for (int j = 0; j < 4; j++) acc[mt][nt][j] = 0.f;

        #pragma unroll
        for (int mt = 0; mt < 2; mt++) {
            u32 aBase = aRow + (u32)((egrp * 32 + mt * 16) * 128);
            #pragma unroll
            for (int kk = 0; kk < 4; kk++) {
                u32 akx = (u32)((kk * 32 + ak16) ^ axor);
                u32 a0, a1, a2, a3;
                ldsm4(aBase + akx, a0, a1, a2, a3);
                u32 bkx = (u32)((kk * 32 + bk16) ^ bxor);
                #pragma unroll
                for (int np = 0; np < 2; np++) {
                    u32 bh0, bh1, bh2, bh3, bl0, bl1, bl2, bl3;
                    ldsm4(bHrow + np * 2048 + bkx, bh0, bh1, bh2, bh3);
                    ldsm4(bHrow + (EB_L - EB_H) + np * 2048 + bkx, bl0, bl1, bl2, bl3);
                    mma16816h(acc[mt][np * 2 + 0], a0, a1, a2, a3, bh0, bh1);
                    mma16816h(acc[mt][np * 2 + 0], a0, a1, a2, a3, bl0, bl1);
                    mma16816h(acc[mt][np * 2 + 1], a0, a1, a2, a3, bh2, bh3);
                    mma16816h(acc[mt][np * 2 + 1], a0, a1, a2, a3, bl2, bl3);
                }
            }
        }

        // ---- register epilogue: fp16 P gathers + red.v4 scatter ----
        #pragma unroll
        for (int mt = 0; mt < 2; mt++) {
            #pragma unroll
            for (int h = 0; h < 2; h++) {
                int e = egrp * 32 + mt * 16 + h * 8 + (lane >> 2);
                int s = s_sh[e];
                int r = r_sh[e];
                float4 psv = gather4h(&g_Ph[(size_t)s * 512 + dbase]);
                float4 prv = gather4h(&g_Ph[(size_t)r * 512 + 128 + dbase]);
                float4 psm = gather4h(&g_Ph[(size_t)s * 512 + 256 + dbase]);
                float4 prm = gather4h(&g_Ph[(size_t)r * 512 + 384 + dbase]);

                float v0 = acc[mt][0][2 * h + 0] + psv.x + prv.x + bv4.x;
                float v1 = acc[mt][0][2 * h + 1] + psv.y + prv.y + bv4.y;
                float v2 = acc[mt][1][2 * h + 0] + psv.z + prv.z + bv4.z;
                float v3 = acc[mt][1][2 * h + 1] + psv.w + prv.w + bv4.w;
                float m0 = acc[mt][2][2 * h + 0] + psm.x + prm.x + bm4.x;
                float m1 = acc[mt][2][2 * h + 1] + psm.y + prm.y + bm4.y;
                float m2 = acc[mt][3][2 * h + 0] + psm.z + prm.z + bm4.z;
                float m3 = acc[mt][3][2 * h + 1] + psm.w + prm.w + bm4.w;

                float g0 = softplus_f(v0) * sigmoid_f(m0);
                float g1 = softplus_f(v1) * sigmoid_f(m1);
                float g2 = softplus_f(v2) * sigmoid_f(m2);
                float g3 = softplus_f(v3) * sigmoid_f(m3);

                red4(out + (size_t)r * ND + dbase, g0, g1, g2, g3);
            }
        }
        __syncthreads();
    }
}

// ---------------------------------------------------------------------------
extern "C" void kernel_launch(void* const* d_in, const int* in_sizes, int n_in,
                              void* d_out, int out_size) {
    const float* x  = (const float*)d_in[0];
    const int*   ei = (const int*)  d_in[1];
    const float* ef = (const float*)d_in[2];
    const float* Wv = (const float*)d_in[3];
    const float* bv = (const float*)d_in[4];
    const float* Wm = (const float*)d_in[5];
    const float* bm = (const float*)d_in[6];
    float* out = (float*)d_out;

    cudaFuncSetAttribute(node_gemm_kernel,
                         cudaFuncAttributeMaxDynamicSharedMemorySize, NODE_SMEM);
    cudaFuncSetAttribute(edge_kernel,
                         cudaFuncAttributeMaxDynamicSharedMemorySize, EDGE_SMEM);

    pack_weights_kernel<<<256, 256>>>(Wv, Wm);

    int n4 = N_NODES * ND / 4;
    zero_out_kernel<<<(n4 + 255) / 256, 256>>>((float4*)out, n4);

    node_gemm_kernel<<<dim3(74, 2), 512, NODE_SMEM>>>(x);

    edge_kernel<<<dim3(222, 2), 256, EDGE_SMEM>>>(ef, ei, bv, bm, out);
}

// round 10
// speedup vs baseline: 1.5802x; 1.0388x over previous
#include <cuda_runtime.h>
#include <cuda_bf16.h>
#include <cuda_fp16.h>
#include <stdint.h>

#define N_NODES 50000
#define N_EDGES 800000
#define ND 128
#define ED 64
#define HID 320

typedef uint32_t u32;

// ---------------- device globals (allocation-guard safe) -------------------
__device__ __half g_Ph[(size_t)N_NODES * 512];   // node projections [N,512] fp16
__device__ __nv_bfloat16 g_WnH[512 * 128];       // node weights hi [j][k] (bf16x3)
__device__ __nv_bfloat16 g_WnL[512 * 128];       // node weights lo
__device__ __half g_We[256 * 64];                // edge weights fp16 [j][k] (single)

// ---------------- helpers ----------------------------------------------------
__device__ __forceinline__ u32 smem_u32(const void* p) {
    u32 a;
    asm("{ .reg .u64 t; cvta.to.shared.u64 t, %1; cvt.u32.u64 %0, t; }" : "=r"(a) : "l"(p));
    return a;
}
__device__ __forceinline__ void ldsm4(u32 addr, u32& r0, u32& r1, u32& r2, u32& r3) {
    asm volatile("ldmatrix.sync.aligned.m8n8.x4.shared.b16 {%0,%1,%2,%3}, [%4];"
                 : "=r"(r0), "=r"(r1), "=r"(r2), "=r"(r3) : "r"(addr));
}
__device__ __forceinline__ void ldsm2(u32 addr, u32& r0, u32& r1) {
    asm volatile("ldmatrix.sync.aligned.m8n8.x2.shared.b16 {%0,%1}, [%2];"
                 : "=r"(r0), "=r"(r1) : "r"(addr));
}
// bf16 MMA (node kernel)
__device__ __forceinline__ void mma16816(float* d, u32 a0, u32 a1, u32 a2, u32 a3,
                                         u32 b0, u32 b1) {
    asm volatile(
        "mma.sync.aligned.m16n8k16.row.col.f32.bf16.bf16.f32 "
        "{%0,%1,%2,%3}, {%4,%5,%6,%7}, {%8,%9}, {%0,%1,%2,%3};"
        : "+f"(d[0]), "+f"(d[1]), "+f"(d[2]), "+f"(d[3])
        : "r"(a0), "r"(a1), "r"(a2), "r"(a3), "r"(b0), "r"(b1));
}
// fp16 MMA (edge kernel)
__device__ __forceinline__ void mma16816h(float* d, u32 a0, u32 a1, u32 a2, u32 a3,
                                          u32 b0, u32 b1) {
    asm volatile(
        "mma.sync.aligned.m16n8k16.row.col.f32.f16.f16.f32 "
        "{%0,%1,%2,%3}, {%4,%5,%6,%7}, {%8,%9}, {%0,%1,%2,%3};"
        : "+f"(d[0]), "+f"(d[1]), "+f"(d[2]), "+f"(d[3])
        : "r"(a0), "r"(a1), "r"(a2), "r"(a3), "r"(b0), "r"(b1));
}
__device__ __forceinline__ void red4(float* p, float a, float b, float c, float d) {
    asm volatile("red.global.add.v4.f32 [%0], {%1,%2,%3,%4};"
                 :: "l"(p), "f"(a), "f"(b), "f"(c), "f"(d) : "memory");
}
__device__ __forceinline__ void split_bf16(float v, __nv_bfloat16& h, __nv_bfloat16& l) {
    h = __float2bfloat16_rn(v);
    l = __float2bfloat16_rn(v - __bfloat162float(h));
}
__device__ __forceinline__ float softplus_f(float x) {
    return fmaxf(x, 0.f) + __logf(1.f + __expf(-fabsf(x)));
}
__device__ __forceinline__ float sigmoid_f(float x) {
    return __fdividef(1.f, 1.f + __expf(-x));
}
// gather 4 consecutive fp16 P dims -> float4
__device__ __forceinline__ float4 gather4h(const __half* p) {
    uint2 u = *(const uint2*)p;
    __half2 h01 = *(__half2*)&u.x;
    __half2 h23 = *(__half2*)&u.y;
    float2 f01 = __half22float2(h01);
    float2 f23 = __half22float2(h23);
    return make_float4(f01.x, f01.y, f23.x, f23.y);
}

// ---------------------------------------------------------------------------
// pack weights
// ---------------------------------------------------------------------------
__global__ void pack_weights_kernel(const float* __restrict__ Wv,
                                    const float* __restrict__ Wm) {
    int i = blockIdx.x * blockDim.x + threadIdx.x;
    if (i < 512 * 128) {
        int j = i >> 7, k = i & 127;
        float v;
        if (j < 128)      v = Wv[j * HID + k];
        else if (j < 256) v = Wv[(j - 128) * HID + 128 + k];
        else if (j < 384) v = Wm[(j - 256) * HID + k];
        else              v = Wm[(j - 384) * HID + 128 + k];
        __nv_bfloat16 h, l; split_bf16(v, h, l);
        g_WnH[i] = h; g_WnL[i] = l;
    }
    if (i < 256 * 64) {
        int j = i >> 6, k = i & 63;
        float v = (j < 128) ? Wv[j * HID + 256 + k] : Wm[(j - 128) * HID + 256 + k];
        g_We[i] = __float2half_rn(v);
    }
}

__global__ void zero_out_kernel(float4* __restrict__ out, int n4) {
    int i = blockIdx.x * blockDim.x + threadIdx.x;
    if (i < n4) out[i] = make_float4(0.f, 0.f, 0.f, 0.f);
}

// ---------------------------------------------------------------------------
// Node GEMM (HMMA bf16x3, R4 config): tile 128 nodes x 256 j, epilogue -> fp16 P
// ---------------------------------------------------------------------------
#define NSTR 136
#define N_BH 0
#define N_BL 69632
#define N_AH 139264
#define N_AL 174080
#define NODE_SMEM 208896

__global__ __launch_bounds__(512, 1) void node_gemm_kernel(const float* __restrict__ X) {
    extern __shared__ char smem[];
    u32 sb = smem_u32(smem);
    int tid = threadIdx.x, wid = tid >> 5, lane = tid & 31;
    int n0 = blockIdx.y * 256;

    {
        int j = tid >> 1, k0 = (tid & 1) * 64;
        #pragma unroll
        for (int c = 0; c < 64; c += 2) {
            __nv_bfloat162 h2, l2;
            h2.x = g_WnH[(n0 + j) * 128 + k0 + c];
            h2.y = g_WnH[(n0 + j) * 128 + k0 + c + 1];
            l2.x = g_WnL[(n0 + j) * 128 + k0 + c];
            l2.y = g_WnL[(n0 + j) * 128 + k0 + c + 1];
            *(__nv_bfloat162*)(smem + N_BH + (j * NSTR + k0 + c) * 2) = h2;
            *(__nv_bfloat162*)(smem + N_BL + (j * NSTR + k0 + c) * 2) = l2;
        }
    }

    int egrp = wid >> 1, jgrp = wid & 1;
    u32 aH = sb + N_AH + ((egrp * 16 + (lane & 15)) * NSTR + (lane >> 4) * 8) * 2;
    u32 aL = sb + N_AL + ((egrp * 16 + (lane & 15)) * NSTR + (lane >> 4) * 8) * 2;
    u32 bH = sb + N_BH + ((jgrp * 128 + (lane & 7)) * NSTR + (lane & 8)) * 2;
    u32 bL = sb + N_BL + ((jgrp * 128 + (lane & 7)) * NSTR + (lane & 8)) * 2;

    const int ntiles = (N_NODES + 127) / 128;   // 391
    for (int t = blockIdx.x; t < ntiles; t += gridDim.x) {
        int m0 = t * 128;
        {
            int row = tid >> 2, k0 = (tid & 3) * 32;
            int gm = m0 + row;
            #pragma unroll
            for (int c = 0; c < 32; c += 2) {
                float2 xv = make_float2(0.f, 0.f);
                if (gm < N_NODES) xv = *(const float2*)&X[(size_t)gm * ND + k0 + c];
                __nv_bfloat16 h0, l0, h1, l1;
                split_bf16(xv.x, h0, l0); split_bf16(xv.y, h1, l1);
                *(__nv_bfloat162*)(smem + N_AH + (row * NSTR + k0 + c) * 2) = __nv_bfloat162(h0, h1);
                *(__nv_bfloat162*)(smem + N_AL + (row * NSTR + k0 + c) * 2) = __nv_bfloat162(l0, l1);
            }
        }
        __syncthreads();

        float acc[16][4];
        #pragma unroll
        for (int i = 0; i < 16; i++)
            #pragma unroll
            for (int j = 0; j < 4; j++) acc[i][j] = 0.f;

        #pragma unroll
        for (int kk = 0; kk < 8; kk++) {
            u32 ah0, ah1, ah2, ah3, al0, al1, al2, al3;
            ldsm4(aH + kk * 32, ah0, ah1, ah2, ah3);
            ldsm4(aL + kk * 32, al0, al1, al2, al3);
            #pragma unroll
            for (int nt = 0; nt < 16; nt++) {
                u32 bh0, bh1, bl0, bl1;
                ldsm2(bH + nt * (8 * NSTR * 2) + kk * 32, bh0, bh1);
                ldsm2(bL + nt * (8 * NSTR * 2) + kk * 32, bl0, bl1);
                mma16816(acc[nt], ah0, ah1, ah2, ah3, bh0, bh1);
                mma16816(acc[nt], al0, al1, al2, al3, bh0, bh1);
                mma16816(acc[nt], ah0, ah1, ah2, ah3, bl0, bl1);
            }
        }

        int nodeLo = m0 + egrp * 16 + (lane >> 2);
        int jbase = n0 + jgrp * 128 + (lane & 3) * 2;
        #pragma unroll
        for (int nt = 0; nt < 16; nt++) {
            if (nodeLo < N_NODES)
                *(__half2*)&g_Ph[(size_t)nodeLo * 512 + jbase + nt * 8] =
                    __floats2half2_rn(acc[nt][0], acc[nt][1]);
            if (nodeLo + 8 < N_NODES)
                *(__half2*)&g_Ph[(size_t)(nodeLo + 8) * 512 + jbase + nt * 8] =
                    __floats2half2_rn(acc[nt][2], acc[nt][3]);
        }
        __syncthreads();
    }
}

// ---------------------------------------------------------------------------
// Edge kernel v9: SINGLE-term fp16 MMA (A=ef fp16, B=We fp16), fp16 P gathers,
// staging-free register epilogue. Block 256 thr / 8 warps, 3 CTAs/SM.
// Tile 64 edges x 128 j (jhalf class). B smem 16 KB, A 8 KB.
// ---------------------------------------------------------------------------
#define EB_  0                      // 128 rows * 128B = 16384
#define EA_  16384                  // 64 rows * 128B = 8192 -> 24576
#define E_IDX 24576                 // 128 ints -> 25088
#define EDGE_SMEM 25088

__global__ __launch_bounds__(256, 3) void edge_kernel(
    const float* __restrict__ ef, const int* __restrict__ ei,
    const float* __restrict__ b_val, const float* __restrict__ b_mul,
    float* __restrict__ out)
{
    extern __shared__ char smem[];
    u32 sb = smem_u32(smem);
    int tid = threadIdx.x, wid = tid >> 5, lane = tid & 31;
    int jhalf = blockIdx.y;
    int* s_sh = (int*)(smem + E_IDX);
    int* r_sh = s_sh + 64;

    // ---- B fill (once): permuted rows, xor-swizzled, single fp16 ----
    {
        int jl = tid >> 1, k0 = (tid & 1) * 32;
        int jgrp_ = jl >> 5, jj = jl & 31, ntb = jj >> 3, rr = jj & 7;
        int dd = (rr >> 1) * 4 + (ntb & 1) * 2 + (rr & 1);
        int jg = ((ntb < 2) ? 0 : 128) + jhalf * 64 + jgrp_ * 16 + dd;
        int xorm = (jl & 7) << 4;
        #pragma unroll
        for (int c = 0; c < 32; c += 2) {
            u32 off = (u32)(jl * 128) + (u32)(((k0 + c) * 2) ^ xorm);
            __half2 h2;
            h2.x = g_We[jg * 64 + k0 + c]; h2.y = g_We[jg * 64 + k0 + c + 1];
            *(__half2*)(smem + EB_ + off) = h2;
        }
    }
    __syncthreads();

    int egrp = wid >> 2, jgrp = wid & 3;

    int jrow = jgrp * 32 + ((lane >> 4) & 1) * 8 + (lane & 7);
    u32 bRow = sb + EB_ + (u32)(jrow * 128);
    int bxor = (jrow & 7) << 4;
    int bk16 = ((lane >> 3) & 1) * 16;

    u32 aRow = sb + EA_ + (u32)((lane & 15) * 128);
    int axor = (lane & 7) << 4;
    int ak16 = (lane >> 4) * 16;

    int q = lane & 3;
    int dbase = jhalf * 64 + jgrp * 16 + q * 4;
    const float4 bv4 = *(const float4*)&b_val[dbase];
    const float4 bm4 = *(const float4*)&b_mul[dbase];

    const int ntiles = N_EDGES / 64;   // 12500
    for (int tile = blockIdx.x; tile < ntiles; tile += gridDim.x) {
        int e0 = tile * 64;
        if (tid < 64)       s_sh[tid] = ei[e0 + tid];
        else if (tid < 128) r_sh[tid - 64] = ei[N_EDGES + e0 + tid - 64];

        // A fill: ef tile [64 e][64 k] -> fp16, swizzled 128B rows
        {
            int e = tid >> 2, k0 = (tid & 3) * 16;
            int xm = (e & 7) << 4;
            const float2* src = (const float2*)&ef[(size_t)(e0 + e) * ED + k0];
            #pragma unroll
            for (int c = 0; c < 16; c += 2) {
                float2 xv = src[c >> 1];
                u32 off = (u32)(e * 128) + (u32)(((k0 + c) * 2) ^ xm);
                *(__half2*)(smem + EA_ + off) = __floats2half2_rn(xv.x, xv.y);
            }
        }
        __syncthreads();

        float acc[2][4][4];
        #pragma unroll
        for (int mt = 0; mt < 2; mt++)
            #pragma unroll
            for (int nt = 0; nt < 4; nt++)
                #pragma unroll
                for (int j = 0; j < 4; j++) acc[mt][nt][j] = 0.f;

        #pragma unroll
        for (int mt = 0; mt < 2; mt++) {
            u32 aBase = aRow + (u32)((egrp * 32 + mt * 16) * 128);
            #pragma unroll
            for (int kk = 0; kk < 4; kk++) {
                u32 akx = (u32)((kk * 32 + ak16) ^ axor);
                u32 a0, a1, a2, a3;
                ldsm4(aBase + akx, a0, a1, a2, a3);
                u32 bkx = (u32)((kk * 32 + bk16) ^ bxor);
                #pragma unroll
                for (int np = 0; np < 2; np++) {
                    u32 b0, b1, b2, b3;
                    ldsm4(bRow + np * 2048 + bkx, b0, b1, b2, b3);
                    mma16816h(acc[mt][np * 2 + 0], a0, a1, a2, a3, b0, b1);
                    mma16816h(acc[mt][np * 2 + 1], a0, a1, a2, a3, b2, b3);
                }
            }
        }

        // ---- register epilogue: fp16 P gathers + red.v4 scatter ----
        #pragma unroll
        for (int mt = 0; mt < 2; mt++) {
            #pragma unroll
            for (int h = 0; h < 2; h++) {
                int e = egrp * 32 + mt * 16 + h * 8 + (lane >> 2);
                int s = s_sh[e];
                int r = r_sh[e];
                float4 psv = gather4h(&g_Ph[(size_t)s * 512 + dbase]);
                float4 prv = gather4h(&g_Ph[(size_t)r * 512 + 128 + dbase]);
                float4 psm = gather4h(&g_Ph[(size_t)s * 512 + 256 + dbase]);
                float4 prm = gather4h(&g_Ph[(size_t)r * 512 + 384 + dbase]);

                float v0 = acc[mt][0][2 * h + 0] + psv.x + prv.x + bv4.x;
                float v1 = acc[mt][0][2 * h + 1] + psv.y + prv.y + bv4.y;
                float v2 = acc[mt][1][2 * h + 0] + psv.z + prv.z + bv4.z;
                float v3 = acc[mt][1][2 * h + 1] + psv.w + prv.w + bv4.w;
                float m0 = acc[mt][2][2 * h + 0] + psm.x + prm.x + bm4.x;
                float m1 = acc[mt][2][2 * h + 1] + psm.y + prm.y + bm4.y;
                float m2 = acc[mt][3][2 * h + 0] + psm.z + prm.z + bm4.z;
                float m3 = acc[mt][3][2 * h + 1] + psm.w + prm.w + bm4.w;

                float g0 = softplus_f(v0) * sigmoid_f(m0);
                float g1 = softplus_f(v1) * sigmoid_f(m1);
                float g2 = softplus_f(v2) * sigmoid_f(m2);
                float g3 = softplus_f(v3) * sigmoid_f(m3);

                red4(out + (size_t)r * ND + dbase, g0, g1, g2, g3);
            }
        }
        __syncthreads();
    }
}

// ---------------------------------------------------------------------------
extern "C" void kernel_launch(void* const* d_in, const int* in_sizes, int n_in,
                              void* d_out, int out_size) {
    const float* x  = (const float*)d_in[0];
    const int*   ei = (const int*)  d_in[1];
    const float* ef = (const float*)d_in[2];
    const float* Wv = (const float*)d_in[3];
    const float* bv = (const float*)d_in[4];
    const float* Wm = (const float*)d_in[5];
    const float* bm = (const float*)d_in[6];
    float* out = (float*)d_out;

    cudaFuncSetAttribute(node_gemm_kernel,
                         cudaFuncAttributeMaxDynamicSharedMemorySize, NODE_SMEM);
    cudaFuncSetAttribute(edge_kernel,
                         cudaFuncAttributeMaxDynamicSharedMemorySize, EDGE_SMEM);

    pack_weights_kernel<<<256, 256>>>(Wv, Wm);

    int n4 = N_NODES * ND / 4;
    zero_out_kernel<<<(n4 + 255) / 256, 256>>>((float4*)out, n4);

    node_gemm_kernel<<<dim3(74, 2), 512, NODE_SMEM>>>(x);

    edge_kernel<<<dim3(222, 2), 256, EDGE_SMEM>>>(ef, ei, bv, bm, out);
}

// round 11
// speedup vs baseline: 1.9513x; 1.2349x over previous
#include <cuda_runtime.h>
#include <cuda_bf16.h>
#include <cuda_fp16.h>
#include <stdint.h>

#define N_NODES 50000
#define N_EDGES 800000
#define ND 128
#define ED 64
#define HID 320

typedef uint32_t u32;

// ---------------- device globals (allocation-guard safe) -------------------
__device__ __half g_Ph[(size_t)N_NODES * 512];   // node projections [N,512] fp16
__device__ __half g_Wn[512 * 128];               // node weights fp16 [j][k] (single)
__device__ __half g_We[256 * 64];                // edge weights fp16 [j][k] (single)

// ---------------- helpers ----------------------------------------------------
__device__ __forceinline__ u32 smem_u32(const void* p) {
    u32 a;
    asm("{ .reg .u64 t; cvta.to.shared.u64 t, %1; cvt.u32.u64 %0, t; }" : "=r"(a) : "l"(p));
    return a;
}
__device__ __forceinline__ void ldsm4(u32 addr, u32& r0, u32& r1, u32& r2, u32& r3) {
    asm volatile("ldmatrix.sync.aligned.m8n8.x4.shared.b16 {%0,%1,%2,%3}, [%4];"
                 : "=r"(r0), "=r"(r1), "=r"(r2), "=r"(r3) : "r"(addr));
}
__device__ __forceinline__ void ldsm2(u32 addr, u32& r0, u32& r1) {
    asm volatile("ldmatrix.sync.aligned.m8n8.x2.shared.b16 {%0,%1}, [%2];"
                 : "=r"(r0), "=r"(r1) : "r"(addr));
}
// fp16 MMA
__device__ __forceinline__ void mma16816h(float* d, u32 a0, u32 a1, u32 a2, u32 a3,
                                          u32 b0, u32 b1) {
    asm volatile(
        "mma.sync.aligned.m16n8k16.row.col.f32.f16.f16.f32 "
        "{%0,%1,%2,%3}, {%4,%5,%6,%7}, {%8,%9}, {%0,%1,%2,%3};"
        : "+f"(d[0]), "+f"(d[1]), "+f"(d[2]), "+f"(d[3])
        : "r"(a0), "r"(a1), "r"(a2), "r"(a3), "r"(b0), "r"(b1));
}
__device__ __forceinline__ void red4(float* p, float a, float b, float c, float d) {
    asm volatile("red.global.add.v4.f32 [%0], {%1,%2,%3,%4};"
                 :: "l"(p), "f"(a), "f"(b), "f"(c), "f"(d) : "memory");
}
__device__ __forceinline__ void split_f16(float v, __half& h, __half& l) {
    h = __float2half_rn(v);
    l = __float2half_rn(v - __half2float(h));
}
__device__ __forceinline__ float softplus_f(float x) {
    return fmaxf(x, 0.f) + __logf(1.f + __expf(-fabsf(x)));
}
__device__ __forceinline__ float sigmoid_f(float x) {
    return __fdividef(1.f, 1.f + __expf(-x));
}
// gather 4 consecutive fp16 P dims -> float4
__device__ __forceinline__ float4 gather4h(const __half* p) {
    uint2 u = *(const uint2*)p;
    __half2 h01 = *(__half2*)&u.x;
    __half2 h23 = *(__half2*)&u.y;
    float2 f01 = __half22float2(h01);
    float2 f23 = __half22float2(h23);
    return make_float4(f01.x, f01.y, f23.x, f23.y);
}

// ---------------------------------------------------------------------------
// pack weights (fp16 single precision for both GEMM B matrices)
// ---------------------------------------------------------------------------
__global__ void pack_weights_kernel(const float* __restrict__ Wv,
                                    const float* __restrict__ Wm) {
    int i = blockIdx.x * blockDim.x + threadIdx.x;
    if (i < 512 * 128) {
        int j = i >> 7, k = i & 127;
        float v;
        if (j < 128)      v = Wv[j * HID + k];
        else if (j < 256) v = Wv[(j - 128) * HID + 128 + k];
        else if (j < 384) v = Wm[(j - 256) * HID + k];
        else              v = Wm[(j - 384) * HID + 128 + k];
        g_Wn[i] = __float2half_rn(v);
    }
    if (i < 256 * 64) {
        int j = i >> 6, k = i & 63;
        float v = (j < 128) ? Wv[j * HID + 256 + k] : Wm[(j - 128) * HID + 256 + k];
        g_We[i] = __float2half_rn(v);
    }
}

__global__ void zero_out_kernel(float4* __restrict__ out, int n4) {
    int i = blockIdx.x * blockDim.x + threadIdx.x;
    if (i < n4) out[i] = make_float4(0.f, 0.f, 0.f, 0.f);
}

// ---------------------------------------------------------------------------
// Node GEMM (fp16 A-split 2-term): P = (Xh + Xl) @ Wn^T, fp16 B single.
// tile 128 nodes x 256 j, 512 thr = 16 warps, warp = 16n x 128j.
// ---------------------------------------------------------------------------
#define NSTR 136
#define N_B  0                      // 256*136*2 = 69632
#define N_AH 69632                  // 128*136*2 = 34816
#define N_AL 104448                 // -> 139264
#define NODE_SMEM 139264

__global__ __launch_bounds__(512, 1) void node_gemm_kernel(const float* __restrict__ X) {
    extern __shared__ char smem[];
    u32 sb = smem_u32(smem);
    int tid = threadIdx.x, wid = tid >> 5, lane = tid & 31;
    int n0 = blockIdx.y * 256;

    // B fill (Wn half [256 j][128 k]) fp16 single, padded rows
    {
        int j = tid >> 1, k0 = (tid & 1) * 64;
        #pragma unroll
        for (int c = 0; c < 64; c += 2) {
            __half2 h2;
            h2.x = g_Wn[(n0 + j) * 128 + k0 + c];
            h2.y = g_Wn[(n0 + j) * 128 + k0 + c + 1];
            *(__half2*)(smem + N_B + (j * NSTR + k0 + c) * 2) = h2;
        }
    }

    int egrp = wid >> 1, jgrp = wid & 1;
    u32 aH = sb + N_AH + ((egrp * 16 + (lane & 15)) * NSTR + (lane >> 4) * 8) * 2;
    u32 aL = sb + N_AL + ((egrp * 16 + (lane & 15)) * NSTR + (lane >> 4) * 8) * 2;
    u32 bB = sb + N_B + ((jgrp * 128 + (lane & 7)) * NSTR + (lane & 8)) * 2;

    const int ntiles = (N_NODES + 127) / 128;   // 391
    for (int t = blockIdx.x; t < ntiles; t += gridDim.x) {
        int m0 = t * 128;
        {
            int row = tid >> 2, k0 = (tid & 3) * 32;
            int gm = m0 + row;
            #pragma unroll
            for (int c = 0; c < 32; c += 2) {
                float2 xv = make_float2(0.f, 0.f);
                if (gm < N_NODES) xv = *(const float2*)&X[(size_t)gm * ND + k0 + c];
                __half h0, l0, h1, l1;
                split_f16(xv.x, h0, l0); split_f16(xv.y, h1, l1);
                *(__half2*)(smem + N_AH + (row * NSTR + k0 + c) * 2) = __half2(h0, h1);
                *(__half2*)(smem + N_AL + (row * NSTR + k0 + c) * 2) = __half2(l0, l1);
            }
        }
        __syncthreads();

        float acc[16][4];
        #pragma unroll
        for (int i = 0; i < 16; i++)
            #pragma unroll
            for (int j = 0; j < 4; j++) acc[i][j] = 0.f;

        #pragma unroll
        for (int kk = 0; kk < 8; kk++) {
            u32 ah0, ah1, ah2, ah3, al0, al1, al2, al3;
            ldsm4(aH + kk * 32, ah0, ah1, ah2, ah3);
            ldsm4(aL + kk * 32, al0, al1, al2, al3);
            #pragma unroll
            for (int nt = 0; nt < 16; nt++) {
                u32 b0, b1;
                ldsm2(bB + nt * (8 * NSTR * 2) + kk * 32, b0, b1);
                mma16816h(acc[nt], ah0, ah1, ah2, ah3, b0, b1);
                mma16816h(acc[nt], al0, al1, al2, al3, b0, b1);
            }
        }

        int nodeLo = m0 + egrp * 16 + (lane >> 2);
        int jbase = n0 + jgrp * 128 + (lane & 3) * 2;
        #pragma unroll
        for (int nt = 0; nt < 16; nt++) {
            if (nodeLo < N_NODES)
                *(__half2*)&g_Ph[(size_t)nodeLo * 512 + jbase + nt * 8] =
                    __floats2half2_rn(acc[nt][0], acc[nt][1]);
            if (nodeLo + 8 < N_NODES)
                *(__half2*)&g_Ph[(size_t)(nodeLo + 8) * 512 + jbase + nt * 8] =
                    __floats2half2_rn(acc[nt][2], acc[nt][3]);
        }
        __syncthreads();
    }
}

// ---------------------------------------------------------------------------
// Edge kernel v10: single-term fp16 MMA, B-ldsm hoisted across mt, next-tile
// A-fill overlapped with the gather/scatter epilogue (double-buffered idx).
// Block 256 thr / 8 warps, 3 CTAs/SM. Tile 64 edges x 128 j (jhalf class).
// ---------------------------------------------------------------------------
#define EB_  0                      // 128 rows * 128B = 16384
#define EA_  16384                  // 64 rows * 128B = 8192 -> 24576
#define E_IDX 24576                 // 2 bufs * 128 ints -> 25600
#define EDGE_SMEM 25600

__global__ __launch_bounds__(256, 3) void edge_kernel(
    const float* __restrict__ ef, const int* __restrict__ ei,
    const float* __restrict__ b_val, const float* __restrict__ b_mul,
    float* __restrict__ out)
{
    extern __shared__ char smem[];
    u32 sb = smem_u32(smem);
    int tid = threadIdx.x, wid = tid >> 5, lane = tid & 31;
    int jhalf = blockIdx.y;
    int* idxb = (int*)(smem + E_IDX);   // [buf][128]: s at +0, r at +64

    // ---- B fill (once): permuted rows, xor-swizzled, single fp16 ----
    {
        int jl = tid >> 1, k0 = (tid & 1) * 32;
        int jgrp_ = jl >> 5, jj = jl & 31, ntb = jj >> 3, rr = jj & 7;
        int dd = (rr >> 1) * 4 + (ntb & 1) * 2 + (rr & 1);
        int jg = ((ntb < 2) ? 0 : 128) + jhalf * 64 + jgrp_ * 16 + dd;
        int xorm = (jl & 7) << 4;
        #pragma unroll
        for (int c = 0; c < 32; c += 2) {
            u32 off = (u32)(jl * 128) + (u32)(((k0 + c) * 2) ^ xorm);
            __half2 h2;
            h2.x = g_We[jg * 64 + k0 + c]; h2.y = g_We[jg * 64 + k0 + c + 1];
            *(__half2*)(smem + EB_ + off) = h2;
        }
    }

    int egrp = wid >> 2, jgrp = wid & 3;

    int jrow = jgrp * 32 + ((lane >> 4) & 1) * 8 + (lane & 7);
    u32 bRow = sb + EB_ + (u32)(jrow * 128);
    int bxor = (jrow & 7) << 4;
    int bk16 = ((lane >> 3) & 1) * 16;

    u32 aRow = sb + EA_ + (u32)((lane & 15) * 128);
    int axor = (lane & 7) << 4;
    int ak16 = (lane >> 4) * 16;

    int q = lane & 3;
    int dbase = jhalf * 64 + jgrp * 16 + q * 4;
    const float4 bv4 = *(const float4*)&b_val[dbase];
    const float4 bm4 = *(const float4*)&b_mul[dbase];

    // A-fill lane mapping (constant)
    int fe = tid >> 2, fk0 = (tid & 3) * 16;
    int fxm = (fe & 7) << 4;

    const int stride = gridDim.x;
    const int ntiles = N_EDGES / 64;   // 12500
    int tile = blockIdx.x;

    // ---- prologue: fill A + idx for first tile ----
    if (tile < ntiles) {
        int e0 = tile * 64;
        if (tid < 64)       idxb[tid] = ei[e0 + tid];
        else if (tid < 128) idxb[tid] = ei[N_EDGES + e0 + tid - 64];
        const float2* src = (const float2*)&ef[(size_t)(e0 + fe) * ED + fk0];
        #pragma unroll
        for (int c = 0; c < 16; c += 2) {
            float2 xv = src[c >> 1];
            u32 off = (u32)(fe * 128) + (u32)(((fk0 + c) * 2) ^ fxm);
            *(__half2*)(smem + EA_ + off) = __floats2half2_rn(xv.x, xv.y);
        }
    }
    __syncthreads();

    int buf = 0;
    for (; tile < ntiles; tile += stride) {
        // ---- MMA: B-fragments shared across both mt slices ----
        float acc[2][4][4];
        #pragma unroll
        for (int mt = 0; mt < 2; mt++)
            #pragma unroll
            for (int nt = 0; nt < 4; nt++)
                #pragma unroll
                for (int j = 0; j < 4; j++) acc[mt][nt][j] = 0.f;

        #pragma unroll
        for (int kk = 0; kk < 4; kk++) {
            u32 akx = (u32)((kk * 32 + ak16) ^ axor);
            u32 p0, p1, p2, p3, q0, q1, q2, q3;
            ldsm4(aRow + (u32)((egrp * 32) * 128) + akx, p0, p1, p2, p3);
            ldsm4(aRow + (u32)((egrp * 32 + 16) * 128) + akx, q0, q1, q2, q3);
            u32 bkx = (u32)((kk * 32 + bk16) ^ bxor);
            #pragma unroll
            for (int np = 0; np < 2; np++) {
                u32 b0, b1, b2, b3;
                ldsm4(bRow + np * 2048 + bkx, b0, b1, b2, b3);
                mma16816h(acc[0][np * 2 + 0], p0, p1, p2, p3, b0, b1);
                mma16816h(acc[0][np * 2 + 1], p0, p1, p2, p3, b2, b3);
                mma16816h(acc[1][np * 2 + 0], q0, q1, q2, q3, b0, b1);
                mma16816h(acc[1][np * 2 + 1], q0, q1, q2, q3, b2, b3);
            }
        }
        __syncthreads();   // A smem consumed; safe to refill

        // ---- overlap: issue next tile's A fill + idx loads BEFORE epilogue ----
        int nxt = tile + stride;
        if (nxt < ntiles) {
            int e0n = nxt * 64;
            int* nb = idxb + (buf ^ 1) * 128;
            if (tid < 64)       nb[tid] = ei[e0n + tid];
            else if (tid < 128) nb[tid] = ei[N_EDGES + e0n + tid - 64];
            const float2* src = (const float2*)&ef[(size_t)(e0n + fe) * ED + fk0];
            #pragma unroll
            for (int c = 0; c < 16; c += 2) {
                float2 xv = src[c >> 1];
                u32 off = (u32)(fe * 128) + (u32)(((fk0 + c) * 2) ^ fxm);
                *(__half2*)(smem + EA_ + off) = __floats2half2_rn(xv.x, xv.y);
            }
        }

        // ---- register epilogue: fp16 P gathers + red.v4 scatter ----
        const int* cb = idxb + buf * 128;
        #pragma unroll
        for (int mt = 0; mt < 2; mt++) {
            #pragma unroll
            for (int h = 0; h < 2; h++) {
                int e = egrp * 32 + mt * 16 + h * 8 + (lane >> 2);
                int s = cb[e];
                int r = cb[64 + e];
                float4 psv = gather4h(&g_Ph[(size_t)s * 512 + dbase]);
                float4 prv = gather4h(&g_Ph[(size_t)r * 512 + 128 + dbase]);
                float4 psm = gather4h(&g_Ph[(size_t)s * 512 + 256 + dbase]);
                float4 prm = gather4h(&g_Ph[(size_t)r * 512 + 384 + dbase]);

                float v0 = acc[mt][0][2 * h + 0] + psv.x + prv.x + bv4.x;
                float v1 = acc[mt][0][2 * h + 1] + psv.y + prv.y + bv4.y;
                float v2 = acc[mt][1][2 * h + 0] + psv.z + prv.z + bv4.z;
                float v3 = acc[mt][1][2 * h + 1] + psv.w + prv.w + bv4.w;
                float m0 = acc[mt][2][2 * h + 0] + psm.x + prm.x + bm4.x;
                float m1 = acc[mt][2][2 * h + 1] + psm.y + prm.y + bm4.y;
                float m2 = acc[mt][3][2 * h + 0] + psm.z + prm.z + bm4.z;
                float m3 = acc[mt][3][2 * h + 1] + psm.w + prm.w + bm4.w;

                float g0 = softplus_f(v0) * sigmoid_f(m0);
                float g1 = softplus_f(v1) * sigmoid_f(m1);
                float g2 = softplus_f(v2) * sigmoid_f(m2);
                float g3 = softplus_f(v3) * sigmoid_f(m3);

                red4(out + (size_t)r * ND + dbase, g0, g1, g2, g3);
            }
        }
        __syncthreads();   // next tile's A fill complete before its MMA
        buf ^= 1;
    }
}

// ---------------------------------------------------------------------------
extern "C" void kernel_launch(void* const* d_in, const int* in_sizes, int n_in,
                              void* d_out, int out_size) {
    const float* x  = (const float*)d_in[0];
    const int*   ei = (const int*)  d_in[1];
    const float* ef = (const float*)d_in[2];
    const float* Wv = (const float*)d_in[3];
    const float* bv = (const float*)d_in[4];
    const float* Wm = (const float*)d_in[5];
    const float* bm = (const float*)d_in[6];
    float* out = (float*)d_out;

    cudaFuncSetAttribute(node_gemm_kernel,
                         cudaFuncAttributeMaxDynamicSharedMemorySize, NODE_SMEM);
    cudaFuncSetAttribute(edge_kernel,
                         cudaFuncAttributeMaxDynamicSharedMemorySize, EDGE_SMEM);

    pack_weights_kernel<<<256, 256>>>(Wv, Wm);

    int n4 = N_NODES * ND / 4;
    zero_out_kernel<<<(n4 + 255) / 256, 256>>>((float4*)out, n4);

    node_gemm_kernel<<<dim3(74, 2), 512, NODE_SMEM>>>(x);

    edge_kernel<<<dim3(222, 2), 256, EDGE_SMEM>>>(ef, ei, bv, bm, out);
}

// round 12
// speedup vs baseline: 2.2297x; 1.1427x over previous
#include <cuda_runtime.h>
#include <cuda_bf16.h>
#include <cuda_fp16.h>
#include <stdint.h>

#define N_NODES 50000
#define N_EDGES 800000
#define ND 128
#define ED 64
#define HID 320

typedef uint32_t u32;

// ---------------- device globals (allocation-guard safe) -------------------
// P layout (fp16, 512 cols/node):
//   [0:256)   sender part:   quad q (dims 4q..4q+3): cols q*8+0..3 = val, q*8+4..7 = mul
//   [256:512) receiver part: same structure
__device__ __half g_Ph[(size_t)N_NODES * 512];
__device__ __half g_Wn[512 * 128];               // node weights fp16, rows = P cols
__device__ __half g_We[256 * 64];                // edge weights fp16 [j][k]

// ---------------- helpers ----------------------------------------------------
__device__ __forceinline__ u32 smem_u32(const void* p) {
    u32 a;
    asm("{ .reg .u64 t; cvta.to.shared.u64 t, %1; cvt.u32.u64 %0, t; }" : "=r"(a) : "l"(p));
    return a;
}
__device__ __forceinline__ void ldsm4(u32 addr, u32& r0, u32& r1, u32& r2, u32& r3) {
    asm volatile("ldmatrix.sync.aligned.m8n8.x4.shared.b16 {%0,%1,%2,%3}, [%4];"
                 : "=r"(r0), "=r"(r1), "=r"(r2), "=r"(r3) : "r"(addr));
}
__device__ __forceinline__ void ldsm2(u32 addr, u32& r0, u32& r1) {
    asm volatile("ldmatrix.sync.aligned.m8n8.x2.shared.b16 {%0,%1}, [%2];"
                 : "=r"(r0), "=r"(r1) : "r"(addr));
}
__device__ __forceinline__ void mma16816h(float* d, u32 a0, u32 a1, u32 a2, u32 a3,
                                          u32 b0, u32 b1) {
    asm volatile(
        "mma.sync.aligned.m16n8k16.row.col.f32.f16.f16.f32 "
        "{%0,%1,%2,%3}, {%4,%5,%6,%7}, {%8,%9}, {%0,%1,%2,%3};"
        : "+f"(d[0]), "+f"(d[1]), "+f"(d[2]), "+f"(d[3])
        : "r"(a0), "r"(a1), "r"(a2), "r"(a3), "r"(b0), "r"(b1));
}
__device__ __forceinline__ void red4(float* p, float a, float b, float c, float d) {
    asm volatile("red.global.add.v4.f32 [%0], {%1,%2,%3,%4};"
                 :: "l"(p), "f"(a), "f"(b), "f"(c), "f"(d) : "memory");
}
__device__ __forceinline__ void split_f16(float v, __half& h, __half& l) {
    h = __float2half_rn(v);
    l = __float2half_rn(v - __half2float(h));
}
__device__ __forceinline__ float softplus_f(float x) {
    return fmaxf(x, 0.f) + __logf(1.f + __expf(-fabsf(x)));
}
__device__ __forceinline__ float sigmoid_f(float x) {
    return __fdividef(1.f, 1.f + __expf(-x));
}

// ---------------------------------------------------------------------------
// pack weights. Wn rows follow the interleaved P layout:
//   p in [0,512): half = p>>8 (0 sender / 1 receiver), q = (p&255)>>3, t = p&7
//   dim d = q*4 + (t&3);  t<4 -> W_val row d, else W_mul row d;
//   source column = half*128 + k  (node-dim part of the weight row)
// ---------------------------------------------------------------------------
__global__ void pack_weights_kernel(const float* __restrict__ Wv,
                                    const float* __restrict__ Wm) {
    int i = blockIdx.x * blockDim.x + threadIdx.x;
    if (i < 512 * 128) {
        int p = i >> 7, k = i & 127;
        int half = p >> 8;
        int q = (p & 255) >> 3, t = p & 7;
        int d = q * 4 + (t & 3);
        const float* W = (t < 4) ? Wv : Wm;
        g_Wn[i] = __float2half_rn(W[d * HID + half * 128 + k]);
    }
    if (i < 256 * 64) {
        int j = i >> 6, k = i & 63;
        float v = (j < 128) ? Wv[j * HID + 256 + k] : Wm[(j - 128) * HID + 256 + k];
        g_We[i] = __float2half_rn(v);
    }
}

__global__ void zero_out_kernel(float4* __restrict__ out, int n4) {
    int i = blockIdx.x * blockDim.x + threadIdx.x;
    if (i < n4) out[i] = make_float4(0.f, 0.f, 0.f, 0.f);
}

// ---------------------------------------------------------------------------
// Node GEMM (fp16 A-split 2-term): P = (Xh + Xl) @ Wn^T, fp16 B single.
// tile 128 nodes x 256 j, 512 thr = 16 warps, warp = 16n x 128j.
// ---------------------------------------------------------------------------
#define NSTR 136
#define N_B  0                      // 256*136*2 = 69632
#define N_AH 69632                  // 128*136*2 = 34816
#define N_AL 104448                 // -> 139264
#define NODE_SMEM 139264

__global__ __launch_bounds__(512, 1) void node_gemm_kernel(const float* __restrict__ X) {
    extern __shared__ char smem[];
    u32 sb = smem_u32(smem);
    int tid = threadIdx.x, wid = tid >> 5, lane = tid & 31;
    int n0 = blockIdx.y * 256;

    {
        int j = tid >> 1, k0 = (tid & 1) * 64;
        #pragma unroll
        for (int c = 0; c < 64; c += 2) {
            __half2 h2;
            h2.x = g_Wn[(n0 + j) * 128 + k0 + c];
            h2.y = g_Wn[(n0 + j) * 128 + k0 + c + 1];
            *(__half2*)(smem + N_B + (j * NSTR + k0 + c) * 2) = h2;
        }
    }

    int egrp = wid >> 1, jgrp = wid & 1;
    u32 aH = sb + N_AH + ((egrp * 16 + (lane & 15)) * NSTR + (lane >> 4) * 8) * 2;
    u32 aL = sb + N_AL + ((egrp * 16 + (lane & 15)) * NSTR + (lane >> 4) * 8) * 2;
    u32 bB = sb + N_B + ((jgrp * 128 + (lane & 7)) * NSTR + (lane & 8)) * 2;

    const int ntiles = (N_NODES + 127) / 128;   // 391
    for (int t = blockIdx.x; t < ntiles; t += gridDim.x) {
        int m0 = t * 128;
        {
            int row = tid >> 2, k0 = (tid & 3) * 32;
            int gm = m0 + row;
            #pragma unroll
            for (int c = 0; c < 32; c += 2) {
                float2 xv = make_float2(0.f, 0.f);
                if (gm < N_NODES) xv = *(const float2*)&X[(size_t)gm * ND + k0 + c];
                __half h0, l0, h1, l1;
                split_f16(xv.x, h0, l0); split_f16(xv.y, h1, l1);
                *(__half2*)(smem + N_AH + (row * NSTR + k0 + c) * 2) = __half2(h0, h1);
                *(__half2*)(smem + N_AL + (row * NSTR + k0 + c) * 2) = __half2(l0, l1);
            }
        }
        __syncthreads();

        float acc[16][4];
        #pragma unroll
        for (int i = 0; i < 16; i++)
            #pragma unroll
            for (int j = 0; j < 4; j++) acc[i][j] = 0.f;

        #pragma unroll
        for (int kk = 0; kk < 8; kk++) {
            u32 ah0, ah1, ah2, ah3, al0, al1, al2, al3;
            ldsm4(aH + kk * 32, ah0, ah1, ah2, ah3);
            ldsm4(aL + kk * 32, al0, al1, al2, al3);
            #pragma unroll
            for (int nt = 0; nt < 16; nt++) {
                u32 b0, b1;
                ldsm2(bB + nt * (8 * NSTR * 2) + kk * 32, b0, b1);
                mma16816h(acc[nt], ah0, ah1, ah2, ah3, b0, b1);
                mma16816h(acc[nt], al0, al1, al2, al3, b0, b1);
            }
        }

        int nodeLo = m0 + egrp * 16 + (lane >> 2);
        int jbase = n0 + jgrp * 128 + (lane & 3) * 2;
        #pragma unroll
        for (int nt = 0; nt < 16; nt++) {
            if (nodeLo < N_NODES)
                *(__half2*)&g_Ph[(size_t)nodeLo * 512 + jbase + nt * 8] =
                    __floats2half2_rn(acc[nt][0], acc[nt][1]);
            if (nodeLo + 8 < N_NODES)
                *(__half2*)&g_Ph[(size_t)(nodeLo + 8) * 512 + jbase + nt * 8] =
                    __floats2half2_rn(acc[nt][2], acc[nt][3]);
        }
        __syncthreads();
    }
}

// ---------------------------------------------------------------------------
// Edge kernel v11: single-term fp16 MMA, paired 16B P gathers (val+mul fused),
// float4 A-fill with 8B swizzled stores, fill-epilogue overlap.
// Block 256 thr / 8 warps, 3 CTAs/SM. Tile 64 edges x 128 j (jhalf class).
// ---------------------------------------------------------------------------
#define EB_  0                      // 128 rows * 128B = 16384
#define EA_  16384                  // 64 rows * 128B = 8192 -> 24576
#define E_IDX 24576                 // 2 bufs * 128 ints -> 25600
#define EDGE_SMEM 25600

__global__ __launch_bounds__(256, 3) void edge_kernel(
    const float* __restrict__ ef, const int* __restrict__ ei,
    const float* __restrict__ b_val, const float* __restrict__ b_mul,
    float* __restrict__ out)
{
    extern __shared__ char smem[];
    u32 sb = smem_u32(smem);
    int tid = threadIdx.x, wid = tid >> 5, lane = tid & 31;
    int jhalf = blockIdx.y;
    int* idxb = (int*)(smem + E_IDX);   // [buf][128]: s at +0, r at +64

    // ---- B fill (once): permuted rows, xor-swizzled, single fp16 ----
    {
        int jl = tid >> 1, k0 = (tid & 1) * 32;
        int jgrp_ = jl >> 5, jj = jl & 31, ntb = jj >> 3, rr = jj & 7;
        int dd = (rr >> 1) * 4 + (ntb & 1) * 2 + (rr & 1);
        int jg = ((ntb < 2) ? 0 : 128) + jhalf * 64 + jgrp_ * 16 + dd;
        int xorm = (jl & 7) << 4;
        #pragma unroll
        for (int c = 0; c < 32; c += 2) {
            u32 off = (u32)(jl * 128) + (u32)(((k0 + c) * 2) ^ xorm);
            __half2 h2;
            h2.x = g_We[jg * 64 + k0 + c]; h2.y = g_We[jg * 64 + k0 + c + 1];
            *(__half2*)(smem + EB_ + off) = h2;
        }
    }

    int egrp = wid >> 2, jgrp = wid & 3;

    int jrow = jgrp * 32 + ((lane >> 4) & 1) * 8 + (lane & 7);
    u32 bRow = sb + EB_ + (u32)(jrow * 128);
    int bxor = (jrow & 7) << 4;
    int bk16 = ((lane >> 3) & 1) * 16;

    u32 aRow = sb + EA_ + (u32)((lane & 15) * 128);
    int axor = (lane & 7) << 4;
    int ak16 = (lane >> 4) * 16;

    int q = lane & 3;
    int dbase = jhalf * 64 + jgrp * 16 + q * 4;
    int dq8 = (dbase >> 2) * 8;             // paired P offset (halfs)
    const float4 bv4 = *(const float4*)&b_val[dbase];
    const float4 bm4 = *(const float4*)&b_mul[dbase];

    // A-fill lane mapping (constant)
    int fe = tid >> 2, fk0 = (tid & 3) * 16;
    int fxm = (fe & 7) << 4;

    const int stride = gridDim.x;
    const int ntiles = N_EDGES / 64;   // 12500
    int tile = blockIdx.x;

    // ---- prologue: fill A + idx for first tile ----
    if (tile < ntiles) {
        int e0 = tile * 64;
        if (tid < 64)       idxb[tid] = ei[e0 + tid];
        else if (tid < 128) idxb[tid] = ei[N_EDGES + e0 + tid - 64];
        const float4* src4 = (const float4*)&ef[(size_t)(e0 + fe) * ED + fk0];
        #pragma unroll
        for (int c = 0; c < 16; c += 4) {
            float4 xv = src4[c >> 2];
            __half2 h01 = __floats2half2_rn(xv.x, xv.y);
            __half2 h23 = __floats2half2_rn(xv.z, xv.w);
            u32 off = (u32)(fe * 128) + (u32)(((fk0 + c) * 2) ^ fxm);
            *(uint2*)(smem + EA_ + off) =
                make_uint2(*(u32*)&h01, *(u32*)&h23);
        }
    }
    __syncthreads();

    int buf = 0;
    for (; tile < ntiles; tile += stride) {
        // ---- MMA: B-fragments shared across both mt slices ----
        float acc[2][4][4];
        #pragma unroll
        for (int mt = 0; mt < 2; mt++)
            #pragma unroll
            for (int nt = 0; nt < 4; nt++)
                #pragma unroll
                for (int j = 0; j < 4; j++) acc[mt][nt][j] = 0.f;

        #pragma unroll
        for (int kk = 0; kk < 4; kk++) {
            u32 akx = (u32)((kk * 32 + ak16) ^ axor);
            u32 p0, p1, p2, p3, q0, q1, q2, q3;
            ldsm4(aRow + (u32)((egrp * 32) * 128) + akx, p0, p1, p2, p3);
            ldsm4(aRow + (u32)((egrp * 32 + 16) * 128) + akx, q0, q1, q2, q3);
            u32 bkx = (u32)((kk * 32 + bk16) ^ bxor);
            #pragma unroll
            for (int np = 0; np < 2; np++) {
                u32 b0, b1, b2, b3;
                ldsm4(bRow + np * 2048 + bkx, b0, b1, b2, b3);
                mma16816h(acc[0][np * 2 + 0], p0, p1, p2, p3, b0, b1);
                mma16816h(acc[0][np * 2 + 1], p0, p1, p2, p3, b2, b3);
                mma16816h(acc[1][np * 2 + 0], q0, q1, q2, q3, b0, b1);
                mma16816h(acc[1][np * 2 + 1], q0, q1, q2, q3, b2, b3);
            }
        }
        __syncthreads();   // A smem consumed; safe to refill

        // ---- overlap: issue next tile's A fill + idx loads BEFORE epilogue ----
        int nxt = tile + stride;
        if (nxt < ntiles) {
            int e0n = nxt * 64;
            int* nb = idxb + (buf ^ 1) * 128;
            if (tid < 64)       nb[tid] = ei[e0n + tid];
            else if (tid < 128) nb[tid] = ei[N_EDGES + e0n + tid - 64];
            const float4* src4 = (const float4*)&ef[(size_t)(e0n + fe) * ED + fk0];
            #pragma unroll
            for (int c = 0; c < 16; c += 4) {
                float4 xv = src4[c >> 2];
                __half2 h01 = __floats2half2_rn(xv.x, xv.y);
                __half2 h23 = __floats2half2_rn(xv.z, xv.w);
                u32 off = (u32)(fe * 128) + (u32)(((fk0 + c) * 2) ^ fxm);
                *(uint2*)(smem + EA_ + off) =
                    make_uint2(*(u32*)&h01, *(u32*)&h23);
            }
        }

        // ---- register epilogue: paired 16B P gathers + red.v4 scatter ----
        const int* cb = idxb + buf * 128;
        #pragma unroll
        for (int mt = 0; mt < 2; mt++) {
            #pragma unroll
            for (int h = 0; h < 2; h++) {
                int e = egrp * 32 + mt * 16 + h * 8 + (lane >> 2);
                int s = cb[e];
                int r = cb[64 + e];
                uint4 us = *(const uint4*)&g_Ph[(size_t)s * 512 + dq8];
                uint4 ur = *(const uint4*)&g_Ph[(size_t)r * 512 + 256 + dq8];
                float2 sv01 = __half22float2(*(__half2*)&us.x);
                float2 sv23 = __half22float2(*(__half2*)&us.y);
                float2 sm01 = __half22float2(*(__half2*)&us.z);
                float2 sm23 = __half22float2(*(__half2*)&us.w);
                float2 rv01 = __half22float2(*(__half2*)&ur.x);
                float2 rv23 = __half22float2(*(__half2*)&ur.y);
                float2 rm01 = __half22float2(*(__half2*)&ur.z);
                float2 rm23 = __half22float2(*(__half2*)&ur.w);

                float v0 = acc[mt][0][2 * h + 0] + sv01.x + rv01.x + bv4.x;
                float v1 = acc[mt][0][2 * h + 1] + sv01.y + rv01.y + bv4.y;
                float v2 = acc[mt][1][2 * h + 0] + sv23.x + rv23.x + bv4.z;
                float v3 = acc[mt][1][2 * h + 1] + sv23.y + rv23.y + bv4.w;
                float m0 = acc[mt][2][2 * h + 0] + sm01.x + rm01.x + bm4.x;
                float m1 = acc[mt][2][2 * h + 1] + sm01.y + rm01.y + bm4.y;
                float m2 = acc[mt][3][2 * h + 0] + sm23.x + rm23.x + bm4.z;
                float m3 = acc[mt][3][2 * h + 1] + sm23.y + rm23.y + bm4.w;

                float g0 = softplus_f(v0) * sigmoid_f(m0);
                float g1 = softplus_f(v1) * sigmoid_f(m1);
                float g2 = softplus_f(v2) * sigmoid_f(m2);
                float g3 = softplus_f(v3) * sigmoid_f(m3);

                red4(out + (size_t)r * ND + dbase, g0, g1, g2, g3);
            }
        }
        __syncthreads();   // next tile's A fill complete before its MMA
        buf ^= 1;
    }
}

// ---------------------------------------------------------------------------
extern "C" void kernel_launch(void* const* d_in, const int* in_sizes, int n_in,
                              void* d_out, int out_size) {
    const float* x  = (const float*)d_in[0];
    const int*   ei = (const int*)  d_in[1];
    const float* ef = (const float*)d_in[2];
    const float* Wv = (const float*)d_in[3];
    const float* bv = (const float*)d_in[4];
    const float* Wm = (const float*)d_in[5];
    const float* bm = (const float*)d_in[6];
    float* out = (float*)d_out;

    cudaFuncSetAttribute(node_gemm_kernel,
                         cudaFuncAttributeMaxDynamicSharedMemorySize, NODE_SMEM);
    cudaFuncSetAttribute(edge_kernel,
                         cudaFuncAttributeMaxDynamicSharedMemorySize, EDGE_SMEM);

    pack_weights_kernel<<<256, 256>>>(Wv, Wm);

    int n4 = N_NODES * ND / 4;
    zero_out_kernel<<<(n4 + 255) / 256, 256>>>((float4*)out, n4);

    node_gemm_kernel<<<dim3(74, 2), 512, NODE_SMEM>>>(x);

    edge_kernel<<<dim3(222, 2), 256, EDGE_SMEM>>>(ef, ei, bv, bm, out);
}